// round 2
// baseline (speedup 1.0000x reference)
#include <cuda_runtime.h>
#include <math.h>
#include <stdint.h>

#define BATCH 2
#define DIM 256
#define HEADS 8
#define HD 32
#define NQ 4096
#define NU 1024
#define TOPK 4
#define NTK 16
#define ATT_SCALE 0.17677669529663687f  // 32^-0.5

// ---------------- scratch (static __device__, no allocation) ----------------
__device__ float g_q[BATCH*HEADS*NQ*HD];
__device__ float g_fk[BATCH*HEADS*NQ*HD];
__device__ float g_fv[BATCH*HEADS*NQ*HD];
__device__ float g_k[BATCH*HEADS*NU*HD];
__device__ float g_v[BATCH*HEADS*NU*HD];
__device__ float g_vt[BATCH*DIM*NU];    // v in (b, c=h*32+d, m) layout
__device__ float g_vpe[BATCH*DIM*NU];
__device__ float g_xout[BATCH*DIM*NQ];  // gated output in (b, c, n) layout
__device__ float g_qmean[BATCH*HEADS*HD];
__device__ int   g_txi[BATCH*HEADS*NTK];

// ---------------- threefry2x32 (exact JAX replication, key = (0,42)) --------
__device__ __forceinline__ void threefry2x32_k42(uint32_t x0, uint32_t x1,
                                                 uint32_t& o0, uint32_t& o1) {
    const uint32_t ks0 = 0u, ks1 = 42u, ks2 = 0u ^ 42u ^ 0x1BD11BDAu;
    x0 += ks0; x1 += ks1;
#define TF_R(r) { x0 += x1; x1 = (x1 << (r)) | (x1 >> (32 - (r))); x1 ^= x0; }
    TF_R(13) TF_R(15) TF_R(26) TF_R(6)
    x0 += ks1; x1 += ks2 + 1u;
    TF_R(17) TF_R(29) TF_R(16) TF_R(24)
    x0 += ks2; x1 += ks0 + 2u;
    TF_R(13) TF_R(15) TF_R(26) TF_R(6)
    x0 += ks0; x1 += ks1 + 3u;
    TF_R(17) TF_R(29) TF_R(16) TF_R(24)
    x0 += ks1; x1 += ks2 + 4u;
    TF_R(13) TF_R(15) TF_R(26) TF_R(6)
    x0 += ks2; x1 += ks0 + 5u;
#undef TF_R
    o0 = x0; o1 = x1;
}

// JAX threefry_partitionable (default since jax 0.4.36): per-element counter
// (hi = l >> 32 = 0, lo = l); 32-bit output = o0 ^ o1.
__device__ __forceinline__ float gumbel_at(uint32_t l) {
    uint32_t o0, o1;
    threefry2x32_k42(0u, l, o0, o1);
    uint32_t bits = o0 ^ o1;
    uint32_t fb = (bits >> 9) | 0x3F800000u;
    float u01 = __uint_as_float(fb) - 1.0f;
    const float TINY = 1.17549435e-38f;
    float u = u01 * (1.0f - TINY) + TINY;
    u = fmaxf(TINY, u);
    return -logf(-logf(u));
}

// ---------------- generic conv1x1 GEMM: out[o][p] = sum_c X[c][p] W[o][c] ----
// mode 0: X = x (P=4096), o<256 -> q (W1/B1), o>=256 -> f_kv (W2/B2)
// mode 1: X = upper (P=1024), W1 = kv_w -> k / v / vt
// mode 2: X = g_xout (P=4096), W1 = proj_w -> dst (b,c,p)
__global__ void __launch_bounds__(256)
gemm_kernel(const float* __restrict__ X,
            const float* __restrict__ W1, const float* __restrict__ B1,
            const float* __restrict__ W2, const float* __restrict__ B2,
            float* __restrict__ dst, int P, int mode)
{
    __shared__ float Xs[16][64];
    __shared__ float Ws[64][17];
    const int b  = blockIdx.z;
    const int p0 = blockIdx.x * 64;
    const int o0 = blockIdx.y * 64;
    const int t  = threadIdx.x;
    const int to = t >> 4;   // 0..15 -> o micro-row group
    const int tp = t & 15;   // 0..15 -> p micro-col group

    const float* Xb = (mode == 2) ? (g_xout + (long)b * DIM * P)
                                  : (X + (long)b * DIM * P);

    float acc[4][4];
#pragma unroll
    for (int i = 0; i < 4; i++)
#pragma unroll
        for (int j = 0; j < 4; j++) acc[i][j] = 0.0f;

    for (int c0 = 0; c0 < DIM; c0 += 16) {
#pragma unroll
        for (int r = 0; r < 4; r++) {
            int idx = t + r * 256;
            int cc = idx >> 6, pp = idx & 63;
            Xs[cc][pp] = Xb[(long)(c0 + cc) * P + p0 + pp];
        }
#pragma unroll
        for (int r = 0; r < 4; r++) {
            int idx = t + r * 256;
            int oo = idx >> 4, cc = idx & 15;
            int o = o0 + oo;
            const float* Wsrc = W1; int orow = o;
            if (mode == 0 && o >= 256) { Wsrc = W2; orow = o - 256; }
            Ws[oo][cc] = Wsrc[orow * DIM + c0 + cc];
        }
        __syncthreads();
#pragma unroll
        for (int cc = 0; cc < 16; cc++) {
            float a[4], xx[4];
#pragma unroll
            for (int i = 0; i < 4; i++) a[i] = Ws[to * 4 + i][cc];
#pragma unroll
            for (int j = 0; j < 4; j++) xx[j] = Xs[cc][tp * 4 + j];
#pragma unroll
            for (int i = 0; i < 4; i++)
#pragma unroll
                for (int j = 0; j < 4; j++) acc[i][j] += a[i] * xx[j];
        }
        __syncthreads();
    }

#pragma unroll
    for (int i = 0; i < 4; i++) {
        int o = o0 + to * 4 + i;
        float bias;
        if (mode == 0 && o >= 256) bias = B2[o - 256];
        else bias = B1[o];
#pragma unroll
        for (int j = 0; j < 4; j++) {
            int p = p0 + tp * 4 + j;
            float val = acc[i][j] + bias;
            if (mode == 0) {
                if (o < 256) {
                    int h = o >> 5, d = o & 31;
                    g_q[(((long)(b * HEADS + h)) * NQ + p) * HD + d] = val;
                } else {
                    int e2 = o - 256;
                    int h = e2 >> 6, e = e2 & 63;
                    if (e < 32)
                        g_fk[(((long)(b * HEADS + h)) * NQ + p) * HD + e] = val;
                    else
                        g_fv[(((long)(b * HEADS + h)) * NQ + p) * HD + (e - 32)] = val;
                }
            } else if (mode == 1) {
                int h = o >> 6, e = o & 63;
                if (e < 32) {
                    g_k[(((long)(b * HEADS + h)) * NU + p) * HD + e] = val;
                } else {
                    int d = e - 32;
                    g_v[(((long)(b * HEADS + h)) * NU + p) * HD + d] = val;
                    g_vt[((long)(b * DIM + h * HD + d)) * NU + p] = val;
                }
            } else {
                dst[((long)(b * DIM + o)) * P + p] = val;
            }
        }
    }
}

// ---------------- qmean: mean over n of q, per (b,h) -----------------------
__global__ void __launch_bounds__(256) qmean_kernel() {
    int bh = blockIdx.x;
    int t = threadIdx.x;
    int d = t & 31, g = t >> 5;
    const float* q = g_q + (long)bh * NQ * HD;
    float s = 0.0f;
    for (int r = g; r < NQ; r += 8) s += q[r * HD + d];
    __shared__ float red[8][32];
    red[g][d] = s;
    __syncthreads();
    if (g == 0) {
        float tot = 0.0f;
#pragma unroll
        for (int i = 0; i < 8; i++) tot += red[i][d];
        g_qmean[bh * HD + d] = tot * (1.0f / (float)NQ);
    }
}

// ---------------- gsim + gumbel + top-4 + txi expand -----------------------
__global__ void __launch_bounds__(256) topk_kernel() {
    int bh = blockIdx.x;
    int t = threadIdx.x;
    __shared__ float qm[HD];
    __shared__ float vals[NU];
    __shared__ float rv[256];
    __shared__ int   ri[256];
    __shared__ int   sel[TOPK];
    if (t < HD) qm[t] = g_qmean[bh * HD + t];
    __syncthreads();
    const float* kp = g_k + (long)bh * NU * HD;
    for (int m = t; m < NU; m += 256) {
        float s = 0.0f;
#pragma unroll
        for (int d = 0; d < HD; d++) s += qm[d] * kp[m * HD + d];
        s *= ATT_SCALE;
        vals[m] = s + gumbel_at((uint32_t)(bh * NU + m));
    }
    __syncthreads();
    for (int it = 0; it < TOPK; it++) {
        float bv = -INFINITY; int bi = 0;
        for (int m = t; m < NU; m += 256)
            if (vals[m] > bv) { bv = vals[m]; bi = m; }
        rv[t] = bv; ri[t] = bi;
        __syncthreads();
        for (int s2 = 128; s2 > 0; s2 >>= 1) {
            if (t < s2) {
                if (rv[t + s2] > rv[t]) { rv[t] = rv[t + s2]; ri[t] = ri[t + s2]; }
            }
            __syncthreads();
        }
        if (t == 0) { sel[it] = ri[0]; vals[ri[0]] = -INFINITY; }
        __syncthreads();
    }
    if (t < NTK) {
        int grp = t / TOPK;   // (dh,dw) group: order matches jax concat
        int kk = t % TOPK;
        int dh = grp >> 1, dw = grp & 1;
        int m = sel[kk];
        int hi = (m >> 5) * 2, wi = (m & 31) * 2;
        g_txi[bh * NTK + t] = (hi + dh) * 64 + (wi + dw);
    }
}

// ---------------- fused attention: coarse flash + fine + gate + combine ----
__global__ void __launch_bounds__(256)
attn_kernel(const float* __restrict__ gate_w, const float* __restrict__ gate_b)
{
    const int bh = blockIdx.y;
    const int n0 = blockIdx.x * 64;
    const int t  = threadIdx.x;
    const int to = t >> 4;   // q group: q0 = to*4
    const int tm = t & 15;   // m group (scores) / d group (AV)

    __shared__ float Qt[32][65];   // Qt[d][q]
    __shared__ float Ps[64][65];   // p-matrix, later coarse[q][d] then out
    __shared__ union {
        struct { float Kt[32][65]; float Vs[64][32]; } c;
        struct { float tk[NTK][32]; float tv[NTK][32];
                 float Gs[32][64]; float gb[32]; int txi[NTK]; } f;
    } u;

    // load Q tile transposed
    const float* qg = g_q + ((long)bh * NQ + n0) * HD;
    for (int idx = t; idx < 64 * 32; idx += 256) {
        int qq = idx >> 5, d = idx & 31;
        Qt[d][qq] = qg[idx];
    }

    float acc[4][2];
    float runmax[4], runl[4];
#pragma unroll
    for (int i = 0; i < 4; i++) {
        acc[i][0] = acc[i][1] = 0.0f;
        runmax[i] = -INFINITY; runl[i] = 0.0f;
    }

    const float* kg = g_k + (long)bh * NU * HD;
    const float* vg = g_v + (long)bh * NU * HD;

    for (int m0g = 0; m0g < NU; m0g += 64) {
        __syncthreads();
        for (int idx = t; idx < 64 * 32; idx += 256) {
            int mm = idx >> 5, d = idx & 31;
            u.c.Kt[d][mm] = kg[(long)(m0g + mm) * HD + d];
            u.c.Vs[mm][d] = vg[(long)(m0g + mm) * HD + d];
        }
        __syncthreads();

        float s[4][4];
#pragma unroll
        for (int i = 0; i < 4; i++)
#pragma unroll
            for (int j = 0; j < 4; j++) s[i][j] = 0.0f;
#pragma unroll
        for (int d = 0; d < 32; d++) {
            float a[4], bb[4];
#pragma unroll
            for (int i = 0; i < 4; i++) a[i] = Qt[d][to * 4 + i];
#pragma unroll
            for (int j = 0; j < 4; j++) bb[j] = u.c.Kt[d][tm * 4 + j];
#pragma unroll
            for (int i = 0; i < 4; i++)
#pragma unroll
                for (int j = 0; j < 4; j++) s[i][j] += a[i] * bb[j];
        }
#pragma unroll
        for (int i = 0; i < 4; i++) {
#pragma unroll
            for (int j = 0; j < 4; j++) s[i][j] *= ATT_SCALE;
            float cm = fmaxf(fmaxf(s[i][0], s[i][1]), fmaxf(s[i][2], s[i][3]));
#pragma unroll
            for (int off = 8; off >= 1; off >>= 1)
                cm = fmaxf(cm, __shfl_xor_sync(0xffffffffu, cm, off));
            float nm = fmaxf(runmax[i], cm);
            float alpha = __expf(runmax[i] - nm);
            runmax[i] = nm;
            float rs = 0.0f;
#pragma unroll
            for (int j = 0; j < 4; j++) { s[i][j] = __expf(s[i][j] - nm); rs += s[i][j]; }
#pragma unroll
            for (int off = 8; off >= 1; off >>= 1)
                rs += __shfl_xor_sync(0xffffffffu, rs, off);
            runl[i] = runl[i] * alpha + rs;
            acc[i][0] *= alpha; acc[i][1] *= alpha;
#pragma unroll
            for (int j = 0; j < 4; j++) Ps[to * 4 + i][tm * 4 + j] = s[i][j];
        }
        __syncthreads();
#pragma unroll 8
        for (int m = 0; m < 64; m++) {
            float v0 = u.c.Vs[m][tm * 2], v1 = u.c.Vs[m][tm * 2 + 1];
#pragma unroll
            for (int i = 0; i < 4; i++) {
                float p = Ps[to * 4 + i][m];
                acc[i][0] += p * v0; acc[i][1] += p * v1;
            }
        }
    }
    __syncthreads();
    // write coarse result into Ps[q][d]
#pragma unroll
    for (int i = 0; i < 4; i++) {
        float inv = 1.0f / runl[i];
        Ps[to * 4 + i][tm * 2]     = acc[i][0] * inv;
        Ps[to * 4 + i][tm * 2 + 1] = acc[i][1] * inv;
    }

    // ------- fine phase -------
    if (t < NTK) u.f.txi[t] = g_txi[bh * NTK + t];
    for (int idx = t; idx < 32 * 64; idx += 256)
        u.f.Gs[idx >> 6][idx & 63] = gate_w[idx];
    if (t < 32) u.f.gb[t] = gate_b[t];
    __syncthreads();
    for (int idx = t; idx < NTK * 32; idx += 256) {
        int kk = idx >> 5, d = idx & 31;
        int m = u.f.txi[kk];
        u.f.tk[kk][d] = g_fk[((long)bh * NQ + m) * HD + d];
        u.f.tv[kk][d] = g_fv[((long)bh * NQ + m) * HD + d];
    }
    __syncthreads();

    if (t < 64) {
        const int q = t;
        float sc[NTK];
        float mx = -INFINITY;
#pragma unroll
        for (int kk = 0; kk < NTK; kk++) {
            float s = 0.0f;
#pragma unroll
            for (int d = 0; d < 32; d++) s += Qt[d][q] * u.f.tk[kk][d];
            s *= ATT_SCALE;
            sc[kk] = s; mx = fmaxf(mx, s);
        }
        float sum = 0.0f;
#pragma unroll
        for (int kk = 0; kk < NTK; kk++) { sc[kk] = __expf(sc[kk] - mx); sum += sc[kk]; }
        float inv = 1.0f / sum;
        // refined into Ps[q][32+d]
#pragma unroll
        for (int d = 0; d < 32; d++) {
            float r = 0.0f;
#pragma unroll
            for (int kk = 0; kk < NTK; kk++) r += sc[kk] * u.f.tv[kk][d];
            Ps[q][32 + d] = r * inv;
        }
        // gate (reads Ps[q][0..63]), then combine into Ps[q][d]
        float gv[32];
#pragma unroll
        for (int d = 0; d < 32; d++) {
            float g = u.f.gb[d];
#pragma unroll
            for (int c = 0; c < 64; c++) g += Ps[q][c] * u.f.Gs[d][c];
            gv[d] = 1.0f / (1.0f + __expf(-g));
        }
#pragma unroll
        for (int d = 0; d < 32; d++)
            Ps[q][d] = gv[d] * Ps[q][32 + d] + (1.0f - gv[d]) * Ps[q][d];
    }
    __syncthreads();

    // coalesced write to x_out (b, c=h*32+d, n)
    int b = bh >> 3, h = bh & 7;
    for (int idx = t; idx < 32 * 64; idx += 256) {
        int d = idx >> 6, qq = idx & 63;
        g_xout[((long)(b * DIM + h * HD + d)) * NQ + n0 + qq] = Ps[qq][d];
    }
}

// ---------------- depthwise 7x7 conv on v (32x32), pad 3 -------------------
__global__ void __launch_bounds__(256)
dwconv_kernel(const float* __restrict__ pe_w, const float* __restrict__ pe_b)
{
    int bc = blockIdx.x;      // b*256 + c
    int t = threadIdx.x;
    __shared__ float tile[38 * 38];
    __shared__ float wv[49];
    const float* src = g_vt + (long)bc * NU;
    for (int idx = t; idx < 38 * 38; idx += 256) {
        int ii = idx / 38 - 3, jj = idx % 38 - 3;
        tile[idx] = (ii >= 0 && ii < 32 && jj >= 0 && jj < 32) ? src[ii * 32 + jj] : 0.0f;
    }
    int c = bc & 255;
    if (t < 49) wv[t] = pe_w[c * 49 + t];
    __syncthreads();
    float bias = pe_b[c];
    for (int idx = t; idx < NU; idx += 256) {
        int i = idx >> 5, j = idx & 31;
        float s = bias;
#pragma unroll
        for (int di = 0; di < 7; di++)
#pragma unroll
            for (int dj = 0; dj < 7; dj++)
                s += tile[(i + di) * 38 + (j + dj)] * wv[di * 7 + dj];
        g_vpe[(long)bc * NU + idx] = s;
    }
}

// ---------------- bilinear 2x upsample (jax half-pixel, edge-norm) + add ----
__global__ void __launch_bounds__(256) upadd_kernel() {
    int idx = blockIdx.x * 256 + threadIdx.x;  // B*DIM*NQ = 2097152
    int p = idx & 4095;
    int bc = idx >> 12;
    int I = p >> 6, J = p & 63;
    int i0, i1, j0, j1; float wi0, wi1, wj0, wj1;
    if (I & 1) { i0 = I >> 1; wi0 = 0.75f; i1 = min(i0 + 1, 31); wi1 = 0.25f; }
    else       { i1 = I >> 1; wi1 = 0.75f; i0 = max(i1 - 1, 0);  wi0 = 0.25f; }
    if (J & 1) { j0 = J >> 1; wj0 = 0.75f; j1 = min(j0 + 1, 31); wj1 = 0.25f; }
    else       { j1 = J >> 1; wj1 = 0.75f; j0 = max(j1 - 1, 0);  wj0 = 0.25f; }
    const float* vp = g_vpe + (long)bc * NU;
    float val = wi0 * (wj0 * vp[i0 * 32 + j0] + wj1 * vp[i0 * 32 + j1])
              + wi1 * (wj0 * vp[i1 * 32 + j0] + wj1 * vp[i1 * 32 + j1]);
    g_xout[idx] += val;
}

// ---------------- launch -----------------------------------------------------
extern "C" void kernel_launch(void* const* d_in, const int* in_sizes, int n_in,
                              void* d_out, int out_size)
{
    const float* x      = (const float*)d_in[0];
    const float* upper  = (const float*)d_in[1];
    const float* q_w    = (const float*)d_in[2];
    const float* q_b    = (const float*)d_in[3];
    const float* kv_w   = (const float*)d_in[4];
    const float* kv_b   = (const float*)d_in[5];
    const float* proj_w = (const float*)d_in[6];
    const float* proj_b = (const float*)d_in[7];
    const float* pe_w   = (const float*)d_in[8];
    const float* pe_b   = (const float*)d_in[9];
    const float* gate_w = (const float*)d_in[10];
    const float* gate_b = (const float*)d_in[11];
    float* out = (float*)d_out;

    // q + f_kv from x
    gemm_kernel<<<dim3(64, 12, 2), 256>>>(x, q_w, q_b, kv_w, kv_b, nullptr, NQ, 0);
    // k, v, vt from upper_feat
    gemm_kernel<<<dim3(16, 8, 2), 256>>>(upper, kv_w, kv_b, nullptr, nullptr, nullptr, NU, 1);
    qmean_kernel<<<16, 256>>>();
    topk_kernel<<<16, 256>>>();
    attn_kernel<<<dim3(64, 16), 256>>>(gate_w, gate_b);
    dwconv_kernel<<<BATCH * DIM, 256>>>(pe_w, pe_b);
    upadd_kernel<<<(BATCH * DIM * NQ) / 256, 256>>>();
    // final projection -> d_out
    gemm_kernel<<<dim3(64, 4, 2), 256>>>(nullptr, proj_w, proj_b, nullptr, nullptr, out, NQ, 2);
}

// round 3
// speedup vs baseline: 1.0013x; 1.0013x over previous
#include <cuda_runtime.h>
#include <math.h>
#include <stdint.h>

#define BATCH 2
#define DIM 256
#define HEADS 8
#define HD 32
#define NQ 4096
#define NU 1024
#define TOPK 4
#define NTK 16
#define ATT_SCALE 0.17677669529663687f  // 32^-0.5

// ---------------- scratch (static __device__, no allocation) ----------------
__device__ float g_q[BATCH*HEADS*NQ*HD];
__device__ float g_fk[BATCH*HEADS*NQ*HD];
__device__ float g_fv[BATCH*HEADS*NQ*HD];
__device__ float g_k[BATCH*HEADS*NU*HD];
__device__ float g_v[BATCH*HEADS*NU*HD];
__device__ float g_vt[BATCH*DIM*NU];    // v in (b, c=h*32+d, m) layout
__device__ float g_vpe[BATCH*DIM*NU];
__device__ float g_xout[BATCH*DIM*NQ];  // gated output in (b, c, n) layout
__device__ float g_qmean[BATCH*HEADS*HD];
__device__ int   g_txi[BATCH*HEADS*NTK];

// ---------------- threefry2x32 (exact JAX replication, key = (0,42)) --------
__device__ __forceinline__ void threefry2x32_k42(uint32_t x0, uint32_t x1,
                                                 uint32_t& o0, uint32_t& o1) {
    const uint32_t ks0 = 0u, ks1 = 42u, ks2 = 0u ^ 42u ^ 0x1BD11BDAu;
    x0 += ks0; x1 += ks1;
#define TF_R(r) { x0 += x1; x1 = (x1 << (r)) | (x1 >> (32 - (r))); x1 ^= x0; }
    TF_R(13) TF_R(15) TF_R(26) TF_R(6)
    x0 += ks1; x1 += ks2 + 1u;
    TF_R(17) TF_R(29) TF_R(16) TF_R(24)
    x0 += ks2; x1 += ks0 + 2u;
    TF_R(13) TF_R(15) TF_R(26) TF_R(6)
    x0 += ks0; x1 += ks1 + 3u;
    TF_R(17) TF_R(29) TF_R(16) TF_R(24)
    x0 += ks1; x1 += ks2 + 4u;
    TF_R(13) TF_R(15) TF_R(26) TF_R(6)
    x0 += ks2; x1 += ks0 + 5u;
#undef TF_R
    o0 = x0; o1 = x1;
}

// JAX threefry_partitionable (default since jax 0.4.36): per-element counter
// (hi = l >> 32 = 0, lo = l); 32-bit output = o0 ^ o1.
__device__ __forceinline__ float gumbel_at(uint32_t l) {
    uint32_t o0, o1;
    threefry2x32_k42(0u, l, o0, o1);
    uint32_t bits = o0 ^ o1;
    uint32_t fb = (bits >> 9) | 0x3F800000u;
    float u01 = __uint_as_float(fb) - 1.0f;
    const float TINY = 1.17549435e-38f;
    float u = u01 * (1.0f - TINY) + TINY;
    u = fmaxf(TINY, u);
    return -logf(-logf(u));
}

// ---------------- generic conv1x1 GEMM: out[o][p] = sum_c X[c][p] W[o][c] ----
// mode 0: X = x (P=4096), o<256 -> q (W1/B1), o>=256 -> f_kv (W2/B2)
// mode 1: X = upper (P=1024), W1 = kv_w -> k / v / vt
// mode 2: X = g_xout (P=4096), W1 = proj_w -> dst (b,c,p)
__global__ void __launch_bounds__(256)
gemm_kernel(const float* __restrict__ X,
            const float* __restrict__ W1, const float* __restrict__ B1,
            const float* __restrict__ W2, const float* __restrict__ B2,
            float* __restrict__ dst, int P, int mode)
{
    __shared__ float Xs[16][64];
    __shared__ float Ws[64][17];
    const int b  = blockIdx.z;
    const int p0 = blockIdx.x * 64;
    const int o0 = blockIdx.y * 64;
    const int t  = threadIdx.x;
    const int to = t >> 4;   // 0..15 -> o micro-row group
    const int tp = t & 15;   // 0..15 -> p micro-col group

    const float* Xb = (mode == 2) ? (g_xout + (long)b * DIM * P)
                                  : (X + (long)b * DIM * P);

    float acc[4][4];
#pragma unroll
    for (int i = 0; i < 4; i++)
#pragma unroll
        for (int j = 0; j < 4; j++) acc[i][j] = 0.0f;

    for (int c0 = 0; c0 < DIM; c0 += 16) {
#pragma unroll
        for (int r = 0; r < 4; r++) {
            int idx = t + r * 256;
            int cc = idx >> 6, pp = idx & 63;
            Xs[cc][pp] = Xb[(long)(c0 + cc) * P + p0 + pp];
        }
#pragma unroll
        for (int r = 0; r < 4; r++) {
            int idx = t + r * 256;
            int oo = idx >> 4, cc = idx & 15;
            int o = o0 + oo;
            const float* Wsrc = W1; int orow = o;
            if (mode == 0 && o >= 256) { Wsrc = W2; orow = o - 256; }
            Ws[oo][cc] = Wsrc[orow * DIM + c0 + cc];
        }
        __syncthreads();
#pragma unroll
        for (int cc = 0; cc < 16; cc++) {
            float a[4], xx[4];
#pragma unroll
            for (int i = 0; i < 4; i++) a[i] = Ws[to * 4 + i][cc];
#pragma unroll
            for (int j = 0; j < 4; j++) xx[j] = Xs[cc][tp * 4 + j];
#pragma unroll
            for (int i = 0; i < 4; i++)
#pragma unroll
                for (int j = 0; j < 4; j++) acc[i][j] += a[i] * xx[j];
        }
        __syncthreads();
    }

#pragma unroll
    for (int i = 0; i < 4; i++) {
        int o = o0 + to * 4 + i;
        float bias;
        if (mode == 0 && o >= 256) bias = B2[o - 256];
        else bias = B1[o];
#pragma unroll
        for (int j = 0; j < 4; j++) {
            int p = p0 + tp * 4 + j;
            float val = acc[i][j] + bias;
            if (mode == 0) {
                if (o < 256) {
                    int h = o >> 5, d = o & 31;
                    g_q[(((long)(b * HEADS + h)) * NQ + p) * HD + d] = val;
                } else {
                    int e2 = o - 256;
                    int h = e2 >> 6, e = e2 & 63;
                    if (e < 32)
                        g_fk[(((long)(b * HEADS + h)) * NQ + p) * HD + e] = val;
                    else
                        g_fv[(((long)(b * HEADS + h)) * NQ + p) * HD + (e - 32)] = val;
                }
            } else if (mode == 1) {
                int h = o >> 6, e = o & 63;
                if (e < 32) {
                    g_k[(((long)(b * HEADS + h)) * NU + p) * HD + e] = val;
                } else {
                    int d = e - 32;
                    g_v[(((long)(b * HEADS + h)) * NU + p) * HD + d] = val;
                    g_vt[((long)(b * DIM + h * HD + d)) * NU + p] = val;
                }
            } else {
                dst[((long)(b * DIM + o)) * P + p] = val;
            }
        }
    }
}

// ---------------- qmean: mean over n of q, per (b,h) -----------------------
__global__ void __launch_bounds__(256) qmean_kernel() {
    int bh = blockIdx.x;
    int t = threadIdx.x;
    int d = t & 31, g = t >> 5;
    const float* q = g_q + (long)bh * NQ * HD;
    float s = 0.0f;
    for (int r = g; r < NQ; r += 8) s += q[r * HD + d];
    __shared__ float red[8][32];
    red[g][d] = s;
    __syncthreads();
    if (g == 0) {
        float tot = 0.0f;
#pragma unroll
        for (int i = 0; i < 8; i++) tot += red[i][d];
        g_qmean[bh * HD + d] = tot * (1.0f / (float)NQ);
    }
}

// ---------------- gsim + gumbel + top-4 + txi expand -----------------------
__global__ void __launch_bounds__(256) topk_kernel() {
    int bh = blockIdx.x;
    int t = threadIdx.x;
    __shared__ float qm[HD];
    __shared__ float vals[NU];
    __shared__ float rv[256];
    __shared__ int   ri[256];
    __shared__ int   sel[TOPK];
    if (t < HD) qm[t] = g_qmean[bh * HD + t];
    __syncthreads();
    const float* kp = g_k + (long)bh * NU * HD;
    for (int m = t; m < NU; m += 256) {
        float s = 0.0f;
#pragma unroll
        for (int d = 0; d < HD; d++) s += qm[d] * kp[m * HD + d];
        s *= ATT_SCALE;
        vals[m] = s + gumbel_at((uint32_t)(bh * NU + m));
    }
    __syncthreads();
    for (int it = 0; it < TOPK; it++) {
        float bv = -INFINITY; int bi = 0;
        for (int m = t; m < NU; m += 256)
            if (vals[m] > bv) { bv = vals[m]; bi = m; }
        rv[t] = bv; ri[t] = bi;
        __syncthreads();
        for (int s2 = 128; s2 > 0; s2 >>= 1) {
            if (t < s2) {
                if (rv[t + s2] > rv[t]) { rv[t] = rv[t + s2]; ri[t] = ri[t + s2]; }
            }
            __syncthreads();
        }
        if (t == 0) { sel[it] = ri[0]; vals[ri[0]] = -INFINITY; }
        __syncthreads();
    }
    if (t < NTK) {
        int grp = t / TOPK;   // (dh,dw) group: order matches jax concat
        int kk = t % TOPK;
        int dh = grp >> 1, dw = grp & 1;
        int m = sel[kk];
        int hi = (m >> 5) * 2, wi = (m & 31) * 2;
        g_txi[bh * NTK + t] = (hi + dh) * 64 + (wi + dw);
    }
}

// ---------------- fused attention: coarse flash + fine + gate + combine ----
__global__ void __launch_bounds__(256)
attn_kernel(const float* __restrict__ gate_w, const float* __restrict__ gate_b)
{
    const int bh = blockIdx.y;
    const int n0 = blockIdx.x * 64;
    const int t  = threadIdx.x;
    const int to = t >> 4;   // q group: q0 = to*4
    const int tm = t & 15;   // m group (scores) / d group (AV)

    __shared__ float Qt[32][65];   // Qt[d][q]
    __shared__ float Ps[64][65];   // p-matrix, later coarse[q][d] then out
    __shared__ union {
        struct { float Kt[32][65]; float Vs[64][32]; } c;
        struct { float tk[NTK][32]; float tv[NTK][32];
                 float Gs[32][64]; float gb[32]; int txi[NTK]; } f;
    } u;

    // load Q tile transposed
    const float* qg = g_q + ((long)bh * NQ + n0) * HD;
    for (int idx = t; idx < 64 * 32; idx += 256) {
        int qq = idx >> 5, d = idx & 31;
        Qt[d][qq] = qg[idx];
    }

    float acc[4][2];
    float runmax[4], runl[4];
#pragma unroll
    for (int i = 0; i < 4; i++) {
        acc[i][0] = acc[i][1] = 0.0f;
        runmax[i] = -INFINITY; runl[i] = 0.0f;
    }

    const float* kg = g_k + (long)bh * NU * HD;
    const float* vg = g_v + (long)bh * NU * HD;

    for (int m0g = 0; m0g < NU; m0g += 64) {
        __syncthreads();
        for (int idx = t; idx < 64 * 32; idx += 256) {
            int mm = idx >> 5, d = idx & 31;
            u.c.Kt[d][mm] = kg[(long)(m0g + mm) * HD + d];
            u.c.Vs[mm][d] = vg[(long)(m0g + mm) * HD + d];
        }
        __syncthreads();

        float s[4][4];
#pragma unroll
        for (int i = 0; i < 4; i++)
#pragma unroll
            for (int j = 0; j < 4; j++) s[i][j] = 0.0f;
#pragma unroll
        for (int d = 0; d < 32; d++) {
            float a[4], bb[4];
#pragma unroll
            for (int i = 0; i < 4; i++) a[i] = Qt[d][to * 4 + i];
#pragma unroll
            for (int j = 0; j < 4; j++) bb[j] = u.c.Kt[d][tm * 4 + j];
#pragma unroll
            for (int i = 0; i < 4; i++)
#pragma unroll
                for (int j = 0; j < 4; j++) s[i][j] += a[i] * bb[j];
        }
#pragma unroll
        for (int i = 0; i < 4; i++) {
#pragma unroll
            for (int j = 0; j < 4; j++) s[i][j] *= ATT_SCALE;
            float cm = fmaxf(fmaxf(s[i][0], s[i][1]), fmaxf(s[i][2], s[i][3]));
#pragma unroll
            for (int off = 8; off >= 1; off >>= 1)
                cm = fmaxf(cm, __shfl_xor_sync(0xffffffffu, cm, off));
            float nm = fmaxf(runmax[i], cm);
            float alpha = __expf(runmax[i] - nm);
            runmax[i] = nm;
            float rs = 0.0f;
#pragma unroll
            for (int j = 0; j < 4; j++) { s[i][j] = __expf(s[i][j] - nm); rs += s[i][j]; }
#pragma unroll
            for (int off = 8; off >= 1; off >>= 1)
                rs += __shfl_xor_sync(0xffffffffu, rs, off);
            runl[i] = runl[i] * alpha + rs;
            acc[i][0] *= alpha; acc[i][1] *= alpha;
#pragma unroll
            for (int j = 0; j < 4; j++) Ps[to * 4 + i][tm * 4 + j] = s[i][j];
        }
        __syncthreads();
#pragma unroll 8
        for (int m = 0; m < 64; m++) {
            float v0 = u.c.Vs[m][tm * 2], v1 = u.c.Vs[m][tm * 2 + 1];
#pragma unroll
            for (int i = 0; i < 4; i++) {
                float p = Ps[to * 4 + i][m];
                acc[i][0] += p * v0; acc[i][1] += p * v1;
            }
        }
    }
    __syncthreads();
    // write coarse result into Ps[q][d]
#pragma unroll
    for (int i = 0; i < 4; i++) {
        float inv = 1.0f / runl[i];
        Ps[to * 4 + i][tm * 2]     = acc[i][0] * inv;
        Ps[to * 4 + i][tm * 2 + 1] = acc[i][1] * inv;
    }

    // ------- fine phase -------
    if (t < NTK) u.f.txi[t] = g_txi[bh * NTK + t];
    for (int idx = t; idx < 32 * 64; idx += 256)
        u.f.Gs[idx >> 6][idx & 63] = gate_w[idx];
    if (t < 32) u.f.gb[t] = gate_b[t];
    __syncthreads();
    for (int idx = t; idx < NTK * 32; idx += 256) {
        int kk = idx >> 5, d = idx & 31;
        int m = u.f.txi[kk];
        u.f.tk[kk][d] = g_fk[((long)bh * NQ + m) * HD + d];
        u.f.tv[kk][d] = g_fv[((long)bh * NQ + m) * HD + d];
    }
    __syncthreads();

    if (t < 64) {
        const int q = t;
        float sc[NTK];
        float mx = -INFINITY;
#pragma unroll
        for (int kk = 0; kk < NTK; kk++) {
            float s = 0.0f;
#pragma unroll
            for (int d = 0; d < 32; d++) s += Qt[d][q] * u.f.tk[kk][d];
            s *= ATT_SCALE;
            sc[kk] = s; mx = fmaxf(mx, s);
        }
        float sum = 0.0f;
#pragma unroll
        for (int kk = 0; kk < NTK; kk++) { sc[kk] = __expf(sc[kk] - mx); sum += sc[kk]; }
        float inv = 1.0f / sum;
        // refined into Ps[q][32+d]
#pragma unroll
        for (int d = 0; d < 32; d++) {
            float r = 0.0f;
#pragma unroll
            for (int kk = 0; kk < NTK; kk++) r += sc[kk] * u.f.tv[kk][d];
            Ps[q][32 + d] = r * inv;
        }
        // gate (reads Ps[q][0..63]), then combine into Ps[q][d]
        float gv[32];
#pragma unroll
        for (int d = 0; d < 32; d++) {
            float g = u.f.gb[d];
#pragma unroll
            for (int c = 0; c < 64; c++) g += Ps[q][c] * u.f.Gs[d][c];
            gv[d] = 1.0f / (1.0f + __expf(-g));
        }
#pragma unroll
        for (int d = 0; d < 32; d++)
            Ps[q][d] = gv[d] * Ps[q][32 + d] + (1.0f - gv[d]) * Ps[q][d];
    }
    __syncthreads();

    // coalesced write to x_out (b, c=h*32+d, n)
    int b = bh >> 3, h = bh & 7;
    for (int idx = t; idx < 32 * 64; idx += 256) {
        int d = idx >> 6, qq = idx & 63;
        g_xout[((long)(b * DIM + h * HD + d)) * NQ + n0 + qq] = Ps[qq][d];
    }
}

// ---------------- depthwise 7x7 conv on v (32x32), pad 3 -------------------
__global__ void __launch_bounds__(256)
dwconv_kernel(const float* __restrict__ pe_w, const float* __restrict__ pe_b)
{
    int bc = blockIdx.x;      // b*256 + c
    int t = threadIdx.x;
    __shared__ float tile[38 * 38];
    __shared__ float wv[49];
    const float* src = g_vt + (long)bc * NU;
    for (int idx = t; idx < 38 * 38; idx += 256) {
        int ii = idx / 38 - 3, jj = idx % 38 - 3;
        tile[idx] = (ii >= 0 && ii < 32 && jj >= 0 && jj < 32) ? src[ii * 32 + jj] : 0.0f;
    }
    int c = bc & 255;
    if (t < 49) wv[t] = pe_w[c * 49 + t];
    __syncthreads();
    float bias = pe_b[c];
    for (int idx = t; idx < NU; idx += 256) {
        int i = idx >> 5, j = idx & 31;
        float s = bias;
#pragma unroll
        for (int di = 0; di < 7; di++)
#pragma unroll
            for (int dj = 0; dj < 7; dj++)
                s += tile[(i + di) * 38 + (j + dj)] * wv[di * 7 + dj];
        g_vpe[(long)bc * NU + idx] = s;
    }
}

// ---------------- bilinear 2x upsample (jax half-pixel, edge-norm) + add ----
__global__ void __launch_bounds__(256) upadd_kernel() {
    int idx = blockIdx.x * 256 + threadIdx.x;  // B*DIM*NQ = 2097152
    int p = idx & 4095;
    int bc = idx >> 12;
    int I = p >> 6, J = p & 63;
    int i0, i1, j0, j1; float wi0, wi1, wj0, wj1;
    if (I & 1) { i0 = I >> 1; wi0 = 0.75f; i1 = min(i0 + 1, 31); wi1 = 0.25f; }
    else       { i1 = I >> 1; wi1 = 0.75f; i0 = max(i1 - 1, 0);  wi0 = 0.25f; }
    if (J & 1) { j0 = J >> 1; wj0 = 0.75f; j1 = min(j0 + 1, 31); wj1 = 0.25f; }
    else       { j1 = J >> 1; wj1 = 0.75f; j0 = max(j1 - 1, 0);  wj0 = 0.25f; }
    const float* vp = g_vpe + (long)bc * NU;
    float val = wi0 * (wj0 * vp[i0 * 32 + j0] + wj1 * vp[i0 * 32 + j1])
              + wi1 * (wj0 * vp[i1 * 32 + j0] + wj1 * vp[i1 * 32 + j1]);
    g_xout[idx] += val;
}

// ---------------- launch -----------------------------------------------------
extern "C" void kernel_launch(void* const* d_in, const int* in_sizes, int n_in,
                              void* d_out, int out_size)
{
    const float* x      = (const float*)d_in[0];
    const float* upper  = (const float*)d_in[1];
    const float* q_w    = (const float*)d_in[2];
    const float* q_b    = (const float*)d_in[3];
    const float* kv_w   = (const float*)d_in[4];
    const float* kv_b   = (const float*)d_in[5];
    const float* proj_w = (const float*)d_in[6];
    const float* proj_b = (const float*)d_in[7];
    const float* pe_w   = (const float*)d_in[8];
    const float* pe_b   = (const float*)d_in[9];
    const float* gate_w = (const float*)d_in[10];
    const float* gate_b = (const float*)d_in[11];
    float* out = (float*)d_out;

    // q + f_kv from x
    gemm_kernel<<<dim3(64, 12, 2), 256>>>(x, q_w, q_b, kv_w, kv_b, nullptr, NQ, 0);
    // k, v, vt from upper_feat
    gemm_kernel<<<dim3(16, 8, 2), 256>>>(upper, kv_w, kv_b, nullptr, nullptr, nullptr, NU, 1);
    qmean_kernel<<<16, 256>>>();
    topk_kernel<<<16, 256>>>();
    attn_kernel<<<dim3(64, 16), 256>>>(gate_w, gate_b);
    dwconv_kernel<<<BATCH * DIM, 256>>>(pe_w, pe_b);
    upadd_kernel<<<(BATCH * DIM * NQ) / 256, 256>>>();
    // final projection -> d_out
    gemm_kernel<<<dim3(64, 4, 2), 256>>>(nullptr, proj_w, proj_b, nullptr, nullptr, out, NQ, 2);
}

// round 5
// speedup vs baseline: 1.2054x; 1.2038x over previous
#include <cuda_runtime.h>
#include <math.h>
#include <stdint.h>

#define BATCH 2
#define DIM 256
#define HEADS 8
#define HD 32
#define NQ 4096
#define NU 1024
#define TOPK 4
#define NTK 16
#define ATT_SCALE 0.17677669529663687f  // 32^-0.5

// ---------------- scratch (static __device__, no allocation) ----------------
// transposed layouts [bh][d][n] for coalesced GEMM stores + attn loads
__device__ float g_qT [BATCH*HEADS*HD*NQ];   // pre-scaled by ATT_SCALE
__device__ float g_fkT[BATCH*HEADS*HD*NQ];
__device__ float g_fvT[BATCH*HEADS*HD*NQ];
__device__ float g_kT [BATCH*HEADS*HD*NU];
__device__ float g_v  [BATCH*HEADS*NU*HD];   // natural [bh][m][d] for AV
__device__ float g_vt [BATCH*DIM*NU];        // [b][c][m] for dwconv
__device__ float g_xout[BATCH*DIM*NQ];       // [b][c][n]
__device__ int   g_txi[16*NTK];

// ---------------- threefry2x32, JAX partitionable path, key=(0,42) ----------
__device__ __forceinline__ void threefry2x32_k42(uint32_t x0, uint32_t x1,
                                                 uint32_t& o0, uint32_t& o1) {
    const uint32_t ks0 = 0u, ks1 = 42u, ks2 = 0u ^ 42u ^ 0x1BD11BDAu;
    x0 += ks0; x1 += ks1;
#define TF_R(r) { x0 += x1; x1 = (x1 << (r)) | (x1 >> (32 - (r))); x1 ^= x0; }
    TF_R(13) TF_R(15) TF_R(26) TF_R(6)
    x0 += ks1; x1 += ks2 + 1u;
    TF_R(17) TF_R(29) TF_R(16) TF_R(24)
    x0 += ks2; x1 += ks0 + 2u;
    TF_R(13) TF_R(15) TF_R(26) TF_R(6)
    x0 += ks0; x1 += ks1 + 3u;
    TF_R(17) TF_R(29) TF_R(16) TF_R(24)
    x0 += ks1; x1 += ks2 + 4u;
    TF_R(13) TF_R(15) TF_R(26) TF_R(6)
    x0 += ks2; x1 += ks0 + 5u;
#undef TF_R
    o0 = x0; o1 = x1;
}

__device__ __forceinline__ float gumbel_at(uint32_t l) {
    uint32_t o0, o1;
    threefry2x32_k42(0u, l, o0, o1);
    uint32_t bits = o0 ^ o1;
    uint32_t fb = (bits >> 9) | 0x3F800000u;
    float u01 = __uint_as_float(fb) - 1.0f;
    const float TINY = 1.17549435e-38f;
    float u = u01 * (1.0f - TINY) + TINY;
    u = fmaxf(TINY, u);
    return -logf(-logf(u));
}

// ---------------- GEMM: out[o][p] = sum_c X[c][p] W[o][c] + bias ------------
// 128x128 tile, 8x8 microtile, double-buffered smem.
__global__ void __launch_bounds__(256, 2)
gemm_kernel(const float* __restrict__ X,
            const float* __restrict__ W1, const float* __restrict__ B1,
            const float* __restrict__ W2, const float* __restrict__ B2,
            float* __restrict__ dst, int P, int mode)
{
    __shared__ float Xs[2][8][128];
    __shared__ float Wt[2][8][132];
    const int b  = blockIdx.z;
    const int p0 = blockIdx.x * 128;
    const int o0 = blockIdx.y * 128;
    const int t  = threadIdx.x;
    const int to = t >> 4;     // 16 o-groups of 8
    const int tp = t & 15;     // 16 p-groups of 8

    const int xc  = t >> 5, xp4 = t & 31;   // X stage: row c (8), f4 col (32)
    const int woo = t >> 1, whalf = t & 1;  // W stage: o row (128), c-half (2)

    const float* Xb = (mode == 2) ? (g_xout + (long)b * DIM * P)
                                  : (X + (long)b * DIM * P);
    int ow = o0 + woo;
    const float* wptr;
    if (mode == 0 && ow >= 256) wptr = W2 + (ow - 256) * DIM;
    else                        wptr = W1 + ow * DIM;

    float4 xr = *(const float4*)&Xb[(long)xc * P + p0 + xp4 * 4];
    float4 wr = *(const float4*)&wptr[whalf * 4];

    float acc[8][8];
#pragma unroll
    for (int i = 0; i < 8; i++)
#pragma unroll
        for (int j = 0; j < 8; j++) acc[i][j] = 0.0f;

    int buf = 0;
    for (int c0 = 0; c0 < DIM; c0 += 8) {
        *(float4*)&Xs[buf][xc][xp4 * 4] = xr;
        Wt[buf][whalf * 4 + 0][woo] = wr.x;
        Wt[buf][whalf * 4 + 1][woo] = wr.y;
        Wt[buf][whalf * 4 + 2][woo] = wr.z;
        Wt[buf][whalf * 4 + 3][woo] = wr.w;
        __syncthreads();
        if (c0 + 8 < DIM) {
            xr = *(const float4*)&Xb[(long)(c0 + 8 + xc) * P + p0 + xp4 * 4];
            wr = *(const float4*)&wptr[c0 + 8 + whalf * 4];
        }
#pragma unroll
        for (int k = 0; k < 8; k++) {
            float4 a0 = *(const float4*)&Wt[buf][k][to * 8];
            float4 a1 = *(const float4*)&Wt[buf][k][to * 8 + 4];
            float4 x0 = *(const float4*)&Xs[buf][k][tp * 8];
            float4 x1 = *(const float4*)&Xs[buf][k][tp * 8 + 4];
            float av[8] = {a0.x, a0.y, a0.z, a0.w, a1.x, a1.y, a1.z, a1.w};
            float xv[8] = {x0.x, x0.y, x0.z, x0.w, x1.x, x1.y, x1.z, x1.w};
#pragma unroll
            for (int i = 0; i < 8; i++)
#pragma unroll
                for (int j = 0; j < 8; j++) acc[i][j] += av[i] * xv[j];
        }
        buf ^= 1;
    }

    const int p = p0 + tp * 8;
#pragma unroll
    for (int i = 0; i < 8; i++) {
        int o = o0 + to * 8 + i;
        float bias = (mode == 0 && o >= 256) ? B2[o - 256] : B1[o];
        float r[8];
#pragma unroll
        for (int j = 0; j < 8; j++) r[j] = acc[i][j] + bias;
        if (mode == 0) {
            if (o < 256) {
#pragma unroll
                for (int j = 0; j < 8; j++) r[j] *= ATT_SCALE;
                float* ptr = g_qT + ((long)(b * 8 + (o >> 5)) * 32 + (o & 31)) * NQ + p;
                *(float4*)&ptr[0] = make_float4(r[0], r[1], r[2], r[3]);
                *(float4*)&ptr[4] = make_float4(r[4], r[5], r[6], r[7]);
            } else {
                int e2 = o - 256, h = e2 >> 6, e = e2 & 63;
                float* base = (e < 32) ? g_fkT : g_fvT;
                float* ptr = base + ((long)(b * 8 + h) * 32 + (e & 31)) * NQ + p;
                *(float4*)&ptr[0] = make_float4(r[0], r[1], r[2], r[3]);
                *(float4*)&ptr[4] = make_float4(r[4], r[5], r[6], r[7]);
            }
        } else if (mode == 1) {
            int h = o >> 6, e = o & 63;
            if (e < 32) {
                float* ptr = g_kT + ((long)(b * 8 + h) * 32 + e) * NU + p;
                *(float4*)&ptr[0] = make_float4(r[0], r[1], r[2], r[3]);
                *(float4*)&ptr[4] = make_float4(r[4], r[5], r[6], r[7]);
            } else {
                int d = e - 32;
#pragma unroll
                for (int j = 0; j < 8; j++)
                    g_v[((long)(b * 8 + h) * NU + p + j) * 32 + d] = r[j];
                float* ptr = g_vt + ((long)(b * 256 + h * 32 + d)) * NU + p;
                *(float4*)&ptr[0] = make_float4(r[0], r[1], r[2], r[3]);
                *(float4*)&ptr[4] = make_float4(r[4], r[5], r[6], r[7]);
            }
        } else {
            float* ptr = dst + ((long)(b * 256 + o)) * NQ + p;
            *(float4*)&ptr[0] = make_float4(r[0], r[1], r[2], r[3]);
            *(float4*)&ptr[4] = make_float4(r[4], r[5], r[6], r[7]);
        }
    }
}

// ---------------- fused qmean + gsim + gumbel + top4 + txi ------------------
__global__ void __launch_bounds__(256) topk_kernel() {
    const int bh = blockIdx.x;
    const int t = threadIdx.x;
    const int w = t >> 5, l = t & 31;
    __shared__ float qm[32];
    __shared__ float cv[32];
    __shared__ int   ci[32];
    __shared__ int   sel[TOPK];

    const float* qb = g_qT + (long)bh * 32 * NQ;
#pragma unroll
    for (int dd = 0; dd < 4; dd++) {
        int d = w * 4 + dd;
        float s = 0.0f;
        const float* row = qb + (long)d * NQ;
        for (int i = l; i < NQ; i += 32) s += row[i];
#pragma unroll
        for (int off = 16; off >= 1; off >>= 1)
            s += __shfl_xor_sync(0xffffffffu, s, off);
        if (l == 0) qm[d] = s * (1.0f / (float)NQ);
    }
    __syncthreads();

    const float* kb = g_kT + (long)bh * 32 * NU;
    float v[4]; int id[4];
#pragma unroll
    for (int r = 0; r < 4; r++) {
        int m = t + r * 256;
        float s = 0.0f;
#pragma unroll
        for (int d = 0; d < 32; d++) s += qm[d] * kb[d * NU + m];
        v[r] = s + gumbel_at((uint32_t)(bh * NU + m));
        id[r] = m;
    }

#pragma unroll
    for (int it = 0; it < TOPK; it++) {
        float lv = v[0]; int li = id[0];
#pragma unroll
        for (int r = 1; r < 4; r++) if (v[r] > lv) { lv = v[r]; li = id[r]; }
#pragma unroll
        for (int off = 16; off >= 1; off >>= 1) {
            float ov = __shfl_xor_sync(0xffffffffu, lv, off);
            int   oi = __shfl_xor_sync(0xffffffffu, li, off);
            if (ov > lv) { lv = ov; li = oi; }
        }
#pragma unroll
        for (int r = 0; r < 4; r++) if (id[r] == li) v[r] = -INFINITY;
        if (l == 0) { cv[w * 4 + it] = lv; ci[w * 4 + it] = li; }
    }
    __syncthreads();

    if (t < 32) {
        float lv = cv[t]; int li = ci[t];
#pragma unroll
        for (int it = 0; it < TOPK; it++) {
            float bv = lv; int bi = li;
#pragma unroll
            for (int off = 16; off >= 1; off >>= 1) {
                float ov = __shfl_xor_sync(0xffffffffu, bv, off);
                int   oi = __shfl_xor_sync(0xffffffffu, bi, off);
                if (ov > bv) { bv = ov; bi = oi; }
            }
            if (li == bi) lv = -INFINITY;
            if (t == 0) sel[it] = bi;
        }
    }
    __syncthreads();

    if (t < NTK) {
        int grp = t / TOPK, kk = t % TOPK;
        int dh = grp >> 1, dw = grp & 1;
        int m = sel[kk];
        int hi = (m >> 5) * 2, wi = (m & 31) * 2;
        g_txi[bh * NTK + t] = (hi + dh) * 64 + (wi + dw);
    }
}

// ---------------- fused attention -------------------------------------------
// 128 queries/block. Plain exp (scores ~N(0,1): no max needed).
// smem float offsets (all float4-aligned regions):
#define OFF_QT  0        // [32][132]
#define OFF_KT  4224     // [32][132]
#define OFF_VS  8448     // [128][32]
#define OFF_PT  12544    // P: [128][132] (16896) / OA: [4][128][36] (18432)
#define OFF_LR  30976    // [128]
#define OFF_OUT 31104    // [128][65]
#define OFF_TK  39424    // [16][32]
#define OFF_TV  39936    // [16][32]
#define OFF_GS  40448    // [32][64]
#define OFF_GB  42496    // [32]
#define OFF_TXI 42528    // int[16]
#define ATTN_SMEM_FLOATS 42544

__global__ void __launch_bounds__(256)
attn_kernel(const float* __restrict__ gate_w, const float* __restrict__ gate_b)
{
    extern __shared__ float sm[];
    const int bh = blockIdx.y;
    const int n0 = blockIdx.x * 128;
    const int t  = threadIdx.x;
    const int b = bh >> 3, h = bh & 7;
    const int to = t >> 4, tm = t & 15;            // QK mapping
    const int ms = t >> 6, dg = (t >> 4) & 3, qg = t & 15;  // AV mapping

    // prologue: Q (pre-scaled), gate weights, txi
    const float* qb = g_qT + (long)bh * 32 * NQ + n0;
#pragma unroll
    for (int r = 0; r < 4; r++) {
        int f4 = t + r * 256;
        int d = f4 >> 5, qf = (f4 & 31) << 2;
        *(float4*)&sm[OFF_QT + d * 132 + qf] = *(const float4*)&qb[(long)d * NQ + qf];
    }
#pragma unroll
    for (int r = 0; r < 8; r++) sm[OFF_GS + t + r * 256] = gate_w[t + r * 256];
    if (t < 32) sm[OFF_GB + t] = gate_b[t];
    if (t < NTK) ((int*)sm)[OFF_TXI + t] = g_txi[bh * NTK + t];
    __syncthreads();
    // gather fine keys/values (scattered, small)
#pragma unroll
    for (int r = 0; r < 2; r++) {
        int idx = t + r * 256;
        int kk = idx >> 5, d = idx & 31;
        int m = ((int*)sm)[OFF_TXI + kk];
        sm[OFF_TK + kk * 32 + d] = g_fkT[((long)bh * 32 + d) * NQ + m];
        sm[OFF_TV + kk * 32 + d] = g_fvT[((long)bh * 32 + d) * NQ + m];
    }

    float acc[8][8];
    float runl[8];
#pragma unroll
    for (int i = 0; i < 8; i++) {
        runl[i] = 0.0f;
#pragma unroll
        for (int j = 0; j < 8; j++) acc[i][j] = 0.0f;
    }

    const float* kb = g_kT + (long)bh * 32 * NU;
    const float* vb = g_v  + (long)bh * NU * 32;

    for (int m0 = 0; m0 < NU; m0 += 128) {
        __syncthreads();   // prev AV done (Vs/Pt reusable)
#pragma unroll
        for (int r = 0; r < 4; r++) {
            int f4 = t + r * 256;
            int d = f4 >> 5, mf = (f4 & 31) << 2;
            *(float4*)&sm[OFF_KT + d * 132 + mf] =
                *(const float4*)&kb[(long)d * NU + m0 + mf];
            *(float4*)&sm[OFF_VS + f4 * 4] =
                *(const float4*)&vb[(long)m0 * 32 + f4 * 4];
        }
        __syncthreads();

        // QK 8x8
        float s[8][8];
#pragma unroll
        for (int i = 0; i < 8; i++)
#pragma unroll
            for (int j = 0; j < 8; j++) s[i][j] = 0.0f;
#pragma unroll 4
        for (int k = 0; k < 32; k++) {
            float4 a0 = *(const float4*)&sm[OFF_QT + k * 132 + to * 8];
            float4 a1 = *(const float4*)&sm[OFF_QT + k * 132 + to * 8 + 4];
            float4 b0 = *(const float4*)&sm[OFF_KT + k * 132 + tm * 8];
            float4 b1 = *(const float4*)&sm[OFF_KT + k * 132 + tm * 8 + 4];
            float av[8] = {a0.x, a0.y, a0.z, a0.w, a1.x, a1.y, a1.z, a1.w};
            float bv[8] = {b0.x, b0.y, b0.z, b0.w, b1.x, b1.y, b1.z, b1.w};
#pragma unroll
            for (int i = 0; i < 8; i++)
#pragma unroll
                for (int j = 0; j < 8; j++) s[i][j] += av[i] * bv[j];
        }
        // exp + row-sum partials + swizzled transposed store
#pragma unroll
        for (int i = 0; i < 8; i++)
#pragma unroll
            for (int j = 0; j < 8; j++) {
                s[i][j] = __expf(s[i][j]);
                runl[i] += s[i][j];
            }
#pragma unroll
        for (int j = 0; j < 8; j++) {
            int m = tm * 8 + j;
            int base = OFF_PT + m * 132;
            int sw = tm & 7;
            *(float4*)&sm[base + ((((to * 2)    ) ^ sw) << 2)] =
                make_float4(s[0][j], s[1][j], s[2][j], s[3][j]);
            *(float4*)&sm[base + ((((to * 2) + 1) ^ sw) << 2)] =
                make_float4(s[4][j], s[5][j], s[6][j], s[7][j]);
        }
        __syncthreads();

        // AV 8q x 8d, m split by 4
#pragma unroll 4
        for (int st = 0; st < 32; st++) {
            int m = ms * 32 + st;
            int sw = (m >> 3) & 7;
            float4 p0 = *(const float4*)&sm[OFF_PT + m * 132 + (((qg * 2    ) ^ sw) << 2)];
            float4 p1 = *(const float4*)&sm[OFF_PT + m * 132 + (((qg * 2 + 1) ^ sw) << 2)];
            float4 v0 = *(const float4*)&sm[OFF_VS + m * 32 + dg * 8];
            float4 v1 = *(const float4*)&sm[OFF_VS + m * 32 + dg * 8 + 4];
            float pv[8] = {p0.x, p0.y, p0.z, p0.w, p1.x, p1.y, p1.z, p1.w};
            float vv[8] = {v0.x, v0.y, v0.z, v0.w, v1.x, v1.y, v1.z, v1.w};
#pragma unroll
            for (int i = 0; i < 8; i++)
#pragma unroll
                for (int j = 0; j < 8; j++) acc[i][j] += pv[i] * vv[j];
        }
    }

    // row sums -> lrow
#pragma unroll
    for (int i = 0; i < 8; i++) {
        float r = runl[i];
        r += __shfl_xor_sync(0xffffffffu, r, 8, 16);
        r += __shfl_xor_sync(0xffffffffu, r, 4, 16);
        r += __shfl_xor_sync(0xffffffffu, r, 2, 16);
        r += __shfl_xor_sync(0xffffffffu, r, 1, 16);
        if (tm == 0) sm[OFF_LR + to * 8 + i] = r;
    }
    __syncthreads();   // AV + lrow done; Pt region free

    // park partial acc: OA[ms][q][36]  (stride 36 -> 16B aligned)
#pragma unroll
    for (int i = 0; i < 8; i++) {
        int q = qg * 8 + i;
        int base = OFF_PT + (ms * 128 + q) * 36 + dg * 8;
        *(float4*)&sm[base]     = make_float4(acc[i][0], acc[i][1], acc[i][2], acc[i][3]);
        *(float4*)&sm[base + 4] = make_float4(acc[i][4], acc[i][5], acc[i][6], acc[i][7]);
    }
    __syncthreads();
    // reduce 4 partials -> coarse = Out[q][d]
#pragma unroll
    for (int r = 0; r < 16; r++) {
        int idx = t + r * 256;
        int q = idx >> 5, d = idx & 31;
        float c = sm[OFF_PT + (0 * 128 + q) * 36 + d]
                + sm[OFF_PT + (1 * 128 + q) * 36 + d]
                + sm[OFF_PT + (2 * 128 + q) * 36 + d]
                + sm[OFF_PT + (3 * 128 + q) * 36 + d];
        sm[OFF_OUT + q * 65 + d] = c / sm[OFF_LR + q];
    }
    __syncthreads();

    // fine attention + gate + combine (one thread per query)
    if (t < 128) {
        const int q = t;
        float sc[NTK];
        float sum = 0.0f;
#pragma unroll
        for (int kk = 0; kk < NTK; kk++) {
            float s = 0.0f;
#pragma unroll
            for (int d = 0; d < 32; d++)
                s += sm[OFF_QT + d * 132 + q] * sm[OFF_TK + kk * 32 + d];
            s = __expf(s);
            sc[kk] = s; sum += s;
        }
        float inv = 1.0f / sum;
#pragma unroll
        for (int d = 0; d < 32; d++) {
            float r = 0.0f;
#pragma unroll
            for (int kk = 0; kk < NTK; kk++) r += sc[kk] * sm[OFF_TV + kk * 32 + d];
            sm[OFF_OUT + q * 65 + 32 + d] = r * inv;
        }
        float gv[32];
#pragma unroll
        for (int d = 0; d < 32; d++) {
            float g = sm[OFF_GB + d];
#pragma unroll
            for (int c = 0; c < 64; c++)
                g += sm[OFF_OUT + q * 65 + c] * sm[OFF_GS + d * 64 + c];
            gv[d] = 1.0f / (1.0f + __expf(-g));
        }
#pragma unroll
        for (int d = 0; d < 32; d++) {
            float cr = sm[OFF_OUT + q * 65 + d];
            float rf = sm[OFF_OUT + q * 65 + 32 + d];
            sm[OFF_OUT + q * 65 + d] = gv[d] * rf + (1.0f - gv[d]) * cr;
        }
    }
    __syncthreads();

    // coalesced write to g_xout[b][c][n]
    float* xo = g_xout + ((long)(b * 256 + h * 32)) * NQ + n0;
#pragma unroll
    for (int r = 0; r < 16; r++) {
        int idx = t + r * 256;
        int d = idx >> 7, q = idx & 127;
        xo[(long)d * NQ + q] = sm[OFF_OUT + q * 65 + d];
    }
}

// ---------------- fused depthwise 7x7 + bilinear 2x upsample + add ----------
__global__ void __launch_bounds__(256)
dwupadd_kernel(const float* __restrict__ pe_w, const float* __restrict__ pe_b)
{
    int bc = blockIdx.x;      // b*256 + c
    int t = threadIdx.x;
    __shared__ float tile[38 * 38];
    __shared__ float wv[49];
    __shared__ float vpe[32 * 32];
    const float* src = g_vt + (long)bc * NU;
    for (int idx = t; idx < 38 * 38; idx += 256) {
        int ii = idx / 38 - 3, jj = idx % 38 - 3;
        tile[idx] = (ii >= 0 && ii < 32 && jj >= 0 && jj < 32) ? src[ii * 32 + jj] : 0.0f;
    }
    int c = bc & 255;
    if (t < 49) wv[t] = pe_w[c * 49 + t];
    __syncthreads();
    float bias = pe_b[c];
    for (int idx = t; idx < NU; idx += 256) {
        int i = idx >> 5, j = idx & 31;
        float s = bias;
#pragma unroll
        for (int di = 0; di < 7; di++)
#pragma unroll
            for (int dj = 0; dj < 7; dj++)
                s += tile[(i + di) * 38 + (j + dj)] * wv[di * 7 + dj];
        vpe[idx] = s;
    }
    __syncthreads();
    float* xo = g_xout + (long)bc * NQ;
    for (int idx = t; idx < NQ; idx += 256) {
        int I = idx >> 6, J = idx & 63;
        int i0, i1, j0, j1; float wi0, wi1, wj0, wj1;
        if (I & 1) { i0 = I >> 1; wi0 = 0.75f; i1 = min(i0 + 1, 31); wi1 = 0.25f; }
        else       { i1 = I >> 1; wi1 = 0.75f; i0 = max(i1 - 1, 0);  wi0 = 0.25f; }
        if (J & 1) { j0 = J >> 1; wj0 = 0.75f; j1 = min(j0 + 1, 31); wj1 = 0.25f; }
        else       { j1 = J >> 1; wj1 = 0.75f; j0 = max(j1 - 1, 0);  wj0 = 0.25f; }
        float val = wi0 * (wj0 * vpe[i0 * 32 + j0] + wj1 * vpe[i0 * 32 + j1])
                  + wi1 * (wj0 * vpe[i1 * 32 + j0] + wj1 * vpe[i1 * 32 + j1]);
        xo[idx] += val;
    }
}

// ---------------- launch -----------------------------------------------------
extern "C" void kernel_launch(void* const* d_in, const int* in_sizes, int n_in,
                              void* d_out, int out_size)
{
    const float* x      = (const float*)d_in[0];
    const float* upper  = (const float*)d_in[1];
    const float* q_w    = (const float*)d_in[2];
    const float* q_b    = (const float*)d_in[3];
    const float* kv_w   = (const float*)d_in[4];
    const float* kv_b   = (const float*)d_in[5];
    const float* proj_w = (const float*)d_in[6];
    const float* proj_b = (const float*)d_in[7];
    const float* pe_w   = (const float*)d_in[8];
    const float* pe_b   = (const float*)d_in[9];
    const float* gate_w = (const float*)d_in[10];
    const float* gate_b = (const float*)d_in[11];
    float* out = (float*)d_out;

    cudaFuncSetAttribute(attn_kernel, cudaFuncAttributeMaxDynamicSharedMemorySize,
                         ATTN_SMEM_FLOATS * 4);

    gemm_kernel<<<dim3(32, 6, 2), 256>>>(x, q_w, q_b, kv_w, kv_b, nullptr, NQ, 0);
    gemm_kernel<<<dim3(8, 4, 2), 256>>>(upper, kv_w, kv_b, nullptr, nullptr, nullptr, NU, 1);
    topk_kernel<<<16, 256>>>();
    attn_kernel<<<dim3(32, 16), 256, ATTN_SMEM_FLOATS * 4>>>(gate_w, gate_b);
    dwupadd_kernel<<<BATCH * DIM, 256>>>(pe_w, pe_b);
    gemm_kernel<<<dim3(32, 2, 2), 256>>>(nullptr, proj_w, proj_b, nullptr, nullptr, out, NQ, 2);
}

// round 6
// speedup vs baseline: 1.2778x; 1.0601x over previous
#include <cuda_runtime.h>
#include <math.h>
#include <stdint.h>

#define BATCH 2
#define DIM 256
#define HEADS 8
#define HD 32
#define NQ 4096
#define NU 1024
#define TOPK 4
#define NTK 16
#define ATT_SCALE 0.17677669529663687f  // 32^-0.5

typedef unsigned long long u64;

// ---------------- f32x2 packed math (sm_103a) --------------------------------
__device__ __forceinline__ u64 pack2(float a, float b) {
    u64 r; asm("mov.b64 %0, {%1, %2};" : "=l"(r) : "f"(a), "f"(b)); return r;
}
__device__ __forceinline__ u64 dup2(float a) {
    u64 r; asm("mov.b64 %0, {%1, %1};" : "=l"(r) : "f"(a)); return r;
}
__device__ __forceinline__ void fma2(u64& d, u64 a, u64 b) {
    asm("fma.rn.f32x2 %0, %1, %2, %3;" : "=l"(d) : "l"(a), "l"(b), "l"(d));
}
__device__ __forceinline__ float2 unpk2(u64 v) {
    float2 r; asm("mov.b64 {%0, %1}, %2;" : "=f"(r.x), "=f"(r.y) : "l"(v)); return r;
}

// ---------------- scratch (static __device__, no allocation) ----------------
__device__ float g_qT [BATCH*HEADS*HD*NQ];   // pre-scaled by ATT_SCALE
__device__ float g_fkT[BATCH*HEADS*HD*NQ];
__device__ float g_fvT[BATCH*HEADS*HD*NQ];
__device__ float g_kT [BATCH*HEADS*HD*NU];
__device__ float g_v  [BATCH*HEADS*NU*HD];   // [bh][m][d]
__device__ float g_vt [BATCH*DIM*NU];        // [b][c][m]
__device__ float g_xout[BATCH*DIM*NQ];       // [b][c][n]
__device__ int   g_txi[16*NTK];

// ---------------- threefry2x32, JAX partitionable path, key=(0,42) ----------
__device__ __forceinline__ void threefry2x32_k42(uint32_t x0, uint32_t x1,
                                                 uint32_t& o0, uint32_t& o1) {
    const uint32_t ks0 = 0u, ks1 = 42u, ks2 = 0u ^ 42u ^ 0x1BD11BDAu;
    x0 += ks0; x1 += ks1;
#define TF_R(r) { x0 += x1; x1 = (x1 << (r)) | (x1 >> (32 - (r))); x1 ^= x0; }
    TF_R(13) TF_R(15) TF_R(26) TF_R(6)
    x0 += ks1; x1 += ks2 + 1u;
    TF_R(17) TF_R(29) TF_R(16) TF_R(24)
    x0 += ks2; x1 += ks0 + 2u;
    TF_R(13) TF_R(15) TF_R(26) TF_R(6)
    x0 += ks0; x1 += ks1 + 3u;
    TF_R(17) TF_R(29) TF_R(16) TF_R(24)
    x0 += ks1; x1 += ks2 + 4u;
    TF_R(13) TF_R(15) TF_R(26) TF_R(6)
    x0 += ks2; x1 += ks0 + 5u;
#undef TF_R
    o0 = x0; o1 = x1;
}

__device__ __forceinline__ float gumbel_at(uint32_t l) {
    uint32_t o0, o1;
    threefry2x32_k42(0u, l, o0, o1);
    uint32_t bits = o0 ^ o1;
    uint32_t fb = (bits >> 9) | 0x3F800000u;
    float u01 = __uint_as_float(fb) - 1.0f;
    const float TINY = 1.17549435e-38f;
    float u = u01 * (1.0f - TINY) + TINY;
    u = fmaxf(TINY, u);
    return -logf(-logf(u));
}

// ---------------- GEMM: out[o][p] = sum_c X[c][p] W[o][c] + bias ------------
// 128x128 tile, 8x8 microtile with f32x2 packed FMA, double-buffered smem.
__global__ void __launch_bounds__(256, 2)
gemm_kernel(const float* __restrict__ X,
            const float* __restrict__ W1, const float* __restrict__ B1,
            const float* __restrict__ W2, const float* __restrict__ B2,
            float* __restrict__ dst, int P, int mode)
{
    __shared__ float Xs[2][8][128];
    __shared__ float Wt[2][8][132];
    const int b  = blockIdx.z;
    const int p0 = blockIdx.x * 128;
    const int o0 = blockIdx.y * 128;
    const int t  = threadIdx.x;
    const int to = t >> 4;
    const int tp = t & 15;

    const int xc  = t >> 5, xp4 = t & 31;
    const int woo = t >> 1, whalf = t & 1;

    const float* Xb = (mode == 2) ? (g_xout + (long)b * DIM * P)
                                  : (X + (long)b * DIM * P);
    int ow = o0 + woo;
    const float* wptr;
    if (mode == 0 && ow >= 256) wptr = W2 + (ow - 256) * DIM;
    else                        wptr = W1 + ow * DIM;

    float4 xr = *(const float4*)&Xb[(long)xc * P + p0 + xp4 * 4];
    float4 wr = *(const float4*)&wptr[whalf * 4];

    u64 acc2[8][4];
#pragma unroll
    for (int i = 0; i < 8; i++)
#pragma unroll
        for (int j = 0; j < 4; j++) acc2[i][j] = 0ULL;

    int buf = 0;
    for (int c0 = 0; c0 < DIM; c0 += 8) {
        *(float4*)&Xs[buf][xc][xp4 * 4] = xr;
        Wt[buf][whalf * 4 + 0][woo] = wr.x;
        Wt[buf][whalf * 4 + 1][woo] = wr.y;
        Wt[buf][whalf * 4 + 2][woo] = wr.z;
        Wt[buf][whalf * 4 + 3][woo] = wr.w;
        __syncthreads();
        if (c0 + 8 < DIM) {
            xr = *(const float4*)&Xb[(long)(c0 + 8 + xc) * P + p0 + xp4 * 4];
            wr = *(const float4*)&wptr[c0 + 8 + whalf * 4];
        }
#pragma unroll
        for (int k = 0; k < 8; k++) {
            float4 a0 = *(const float4*)&Wt[buf][k][to * 8];
            float4 a1 = *(const float4*)&Wt[buf][k][to * 8 + 4];
            float4 x0 = *(const float4*)&Xs[buf][k][tp * 8];
            float4 x1 = *(const float4*)&Xs[buf][k][tp * 8 + 4];
            u64 xp[4] = {pack2(x0.x, x0.y), pack2(x0.z, x0.w),
                         pack2(x1.x, x1.y), pack2(x1.z, x1.w)};
            float av[8] = {a0.x, a0.y, a0.z, a0.w, a1.x, a1.y, a1.z, a1.w};
#pragma unroll
            for (int i = 0; i < 8; i++) {
                u64 ad = dup2(av[i]);
#pragma unroll
                for (int j = 0; j < 4; j++) fma2(acc2[i][j], ad, xp[j]);
            }
        }
        buf ^= 1;
    }

    const int p = p0 + tp * 8;
#pragma unroll
    for (int i = 0; i < 8; i++) {
        int o = o0 + to * 8 + i;
        float bias = (mode == 0 && o >= 256) ? B2[o - 256] : B1[o];
        float r[8];
#pragma unroll
        for (int j = 0; j < 4; j++) {
            float2 f = unpk2(acc2[i][j]);
            r[j * 2] = f.x + bias; r[j * 2 + 1] = f.y + bias;
        }
        if (mode == 0) {
            if (o < 256) {
#pragma unroll
                for (int j = 0; j < 8; j++) r[j] *= ATT_SCALE;
                float* ptr = g_qT + ((long)(b * 8 + (o >> 5)) * 32 + (o & 31)) * NQ + p;
                *(float4*)&ptr[0] = make_float4(r[0], r[1], r[2], r[3]);
                *(float4*)&ptr[4] = make_float4(r[4], r[5], r[6], r[7]);
            } else {
                int e2 = o - 256, h = e2 >> 6, e = e2 & 63;
                float* base = (e < 32) ? g_fkT : g_fvT;
                float* ptr = base + ((long)(b * 8 + h) * 32 + (e & 31)) * NQ + p;
                *(float4*)&ptr[0] = make_float4(r[0], r[1], r[2], r[3]);
                *(float4*)&ptr[4] = make_float4(r[4], r[5], r[6], r[7]);
            }
        } else if (mode == 1) {
            int h = o >> 6, e = o & 63;
            if (e < 32) {
                float* ptr = g_kT + ((long)(b * 8 + h) * 32 + e) * NU + p;
                *(float4*)&ptr[0] = make_float4(r[0], r[1], r[2], r[3]);
                *(float4*)&ptr[4] = make_float4(r[4], r[5], r[6], r[7]);
            } else {
                int d = e - 32;
#pragma unroll
                for (int j = 0; j < 8; j++)
                    g_v[((long)(b * 8 + h) * NU + p + j) * 32 + d] = r[j];
                float* ptr = g_vt + ((long)(b * 256 + h * 32 + d)) * NU + p;
                *(float4*)&ptr[0] = make_float4(r[0], r[1], r[2], r[3]);
                *(float4*)&ptr[4] = make_float4(r[4], r[5], r[6], r[7]);
            }
        } else {
            float* ptr = dst + ((long)(b * 256 + o)) * NQ + p;
            *(float4*)&ptr[0] = make_float4(r[0], r[1], r[2], r[3]);
            *(float4*)&ptr[4] = make_float4(r[4], r[5], r[6], r[7]);
        }
    }
}

// ---------------- fused qmean + gsim + gumbel + top4 + txi ------------------
__global__ void __launch_bounds__(256) topk_kernel() {
    const int bh = blockIdx.x;
    const int t = threadIdx.x;
    const int w = t >> 5, l = t & 31;
    __shared__ float qm[32];
    __shared__ float cv[32];
    __shared__ int   ci[32];
    __shared__ int   sel[TOPK];

    const float* qb = g_qT + (long)bh * 32 * NQ;
#pragma unroll
    for (int dd = 0; dd < 4; dd++) {
        int d = w * 4 + dd;
        float s = 0.0f;
        const float* row = qb + (long)d * NQ;
        for (int i = l; i < NQ; i += 32) s += row[i];
#pragma unroll
        for (int off = 16; off >= 1; off >>= 1)
            s += __shfl_xor_sync(0xffffffffu, s, off);
        if (l == 0) qm[d] = s * (1.0f / (float)NQ);
    }
    __syncthreads();

    const float* kb = g_kT + (long)bh * 32 * NU;
    float v[4]; int id[4];
#pragma unroll
    for (int r = 0; r < 4; r++) {
        int m = t + r * 256;
        float s = 0.0f;
#pragma unroll
        for (int d = 0; d < 32; d++) s += qm[d] * kb[d * NU + m];
        v[r] = s + gumbel_at((uint32_t)(bh * NU + m));
        id[r] = m;
    }

#pragma unroll
    for (int it = 0; it < TOPK; it++) {
        float lv = v[0]; int li = id[0];
#pragma unroll
        for (int r = 1; r < 4; r++) if (v[r] > lv) { lv = v[r]; li = id[r]; }
#pragma unroll
        for (int off = 16; off >= 1; off >>= 1) {
            float ov = __shfl_xor_sync(0xffffffffu, lv, off);
            int   oi = __shfl_xor_sync(0xffffffffu, li, off);
            if (ov > lv) { lv = ov; li = oi; }
        }
#pragma unroll
        for (int r = 0; r < 4; r++) if (id[r] == li) v[r] = -INFINITY;
        if (l == 0) { cv[w * 4 + it] = lv; ci[w * 4 + it] = li; }
    }
    __syncthreads();

    if (t < 32) {
        float lv = cv[t]; int li = ci[t];
#pragma unroll
        for (int it = 0; it < TOPK; it++) {
            float bv = lv; int bi = li;
#pragma unroll
            for (int off = 16; off >= 1; off >>= 1) {
                float ov = __shfl_xor_sync(0xffffffffu, bv, off);
                int   oi = __shfl_xor_sync(0xffffffffu, bi, off);
                if (ov > bv) { bv = ov; bi = oi; }
            }
            if (li == bi) lv = -INFINITY;
            if (t == 0) sel[it] = bi;
        }
    }
    __syncthreads();

    if (t < NTK) {
        int grp = t / TOPK, kk = t % TOPK;
        int dh = grp >> 1, dw = grp & 1;
        int m = sel[kk];
        int hi = (m >> 5) * 2, wi = (m & 31) * 2;
        g_txi[bh * NTK + t] = (hi + dh) * 64 + (wi + dw);
    }
}

// ---------------- fused attention (q-block 64, f32x2, 2 blocks/SM) ---------
#define OFF_QT  0        // [32][68]
#define OFF_KT  2176     // [32][132]   (reused as SC[64][17] in fine phase)
#define OFF_VS  6400     // [128][32]
#define OFF_PT  10496    // P: [128][68] (8704) / OA: [4][64][36] (9216)
#define OFF_LR  19712    // [64]
#define OFF_OUT 19776    // [64][65]
#define OFF_TK  23936    // [16][32]
#define OFF_TV  24448    // [16][32]
#define OFF_GS  24960    // [32][64]
#define OFF_GB  27008    // [32]
#define OFF_TXI 27040    // int[16]
#define ATTN_SMEM_FLOATS 27056

__global__ void __launch_bounds__(256, 2)
attn_kernel(const float* __restrict__ gate_w, const float* __restrict__ gate_b)
{
    extern __shared__ float sm[];
    const int bh = blockIdx.y;
    const int n0 = blockIdx.x * 64;
    const int t  = threadIdx.x;
    const int b = bh >> 3, h = bh & 7;
    const int to = t >> 4, tm = t & 15;                       // QK: 4q x (4+4)m
    const int ms = t >> 6, dg = (t >> 4) & 3, qg = t & 15;    // AV: 4q x 8d, 4-way m

    // prologue
    const float* qb = g_qT + (long)bh * 32 * NQ + n0;
#pragma unroll
    for (int r = 0; r < 2; r++) {
        int f4 = t + r * 256;            // 512 f4 = 32 d x 16
        int d = f4 >> 4, qf = (f4 & 15) << 2;
        *(float4*)&sm[OFF_QT + d * 68 + qf] = *(const float4*)&qb[(long)d * NQ + qf];
    }
#pragma unroll
    for (int r = 0; r < 8; r++) sm[OFF_GS + t + r * 256] = gate_w[t + r * 256];
    if (t < 32) sm[OFF_GB + t] = gate_b[t];
    if (t < NTK) ((int*)sm)[OFF_TXI + t] = g_txi[bh * NTK + t];
    __syncthreads();
#pragma unroll
    for (int r = 0; r < 2; r++) {
        int idx = t + r * 256;
        int kk = idx >> 5, d = idx & 31;
        int m = ((int*)sm)[OFF_TXI + kk];
        sm[OFF_TK + kk * 32 + d] = g_fkT[((long)bh * 32 + d) * NQ + m];
        sm[OFF_TV + kk * 32 + d] = g_fvT[((long)bh * 32 + d) * NQ + m];
    }

    u64 acc2[4][4];
    float runl[4];
#pragma unroll
    for (int i = 0; i < 4; i++) {
        runl[i] = 0.0f;
#pragma unroll
        for (int j = 0; j < 4; j++) acc2[i][j] = 0ULL;
    }

    const float* kb = g_kT + (long)bh * 32 * NU;
    const float* vb = g_v  + (long)bh * NU * 32;

    for (int m0 = 0; m0 < NU; m0 += 128) {
        __syncthreads();
        // stage K^T [32][128] and V [128][32]
#pragma unroll
        for (int r = 0; r < 4; r++) {
            int f4 = t + r * 256;        // 1024 f4
            int d = f4 >> 5, mf = (f4 & 31) << 2;
            *(float4*)&sm[OFF_KT + d * 132 + mf] =
                *(const float4*)&kb[(long)d * NU + m0 + mf];
            *(float4*)&sm[OFF_VS + f4 * 4] =
                *(const float4*)&vb[(long)m0 * 32 + f4 * 4];
        }
        __syncthreads();

        // QK: q = to*4+i, m = tm*4+{0..3} and 64+tm*4+{0..3}
        u64 s2[4][4];
#pragma unroll
        for (int i = 0; i < 4; i++)
#pragma unroll
            for (int j = 0; j < 4; j++) s2[i][j] = 0ULL;
#pragma unroll 4
        for (int k = 0; k < 32; k++) {
            float4 a  = *(const float4*)&sm[OFF_QT + k * 68 + to * 4];
            float4 b0 = *(const float4*)&sm[OFF_KT + k * 132 + tm * 4];
            float4 b1 = *(const float4*)&sm[OFF_KT + k * 132 + tm * 4 + 64];
            u64 bp[4] = {pack2(b0.x, b0.y), pack2(b0.z, b0.w),
                         pack2(b1.x, b1.y), pack2(b1.z, b1.w)};
            float av[4] = {a.x, a.y, a.z, a.w};
#pragma unroll
            for (int i = 0; i < 4; i++) {
                u64 ad = dup2(av[i]);
#pragma unroll
                for (int j = 0; j < 4; j++) fma2(s2[i][j], ad, bp[j]);
            }
        }
        // exp + partial row sums
        float e[4][8];
#pragma unroll
        for (int i = 0; i < 4; i++) {
#pragma unroll
            for (int j = 0; j < 4; j++) {
                float2 f = unpk2(s2[i][j]);
                e[i][j * 2]     = __expf(f.x);
                e[i][j * 2 + 1] = __expf(f.y);
                runl[i] += e[i][j * 2] + e[i][j * 2 + 1];
            }
        }
        // transposed store: PT[m][slot], slot = to ^ tm (optimal 4-wf)
        {
            int slot4 = (to ^ tm) << 2;
#pragma unroll
            for (int j = 0; j < 4; j++) {
                int m = tm * 4 + j;
                *(float4*)&sm[OFF_PT + m * 68 + slot4] =
                    make_float4(e[0][j], e[1][j], e[2][j], e[3][j]);
            }
#pragma unroll
            for (int j = 0; j < 4; j++) {
                int m = 64 + tm * 4 + j;
                *(float4*)&sm[OFF_PT + m * 68 + slot4] =
                    make_float4(e[0][4 + j], e[1][4 + j], e[2][4 + j], e[3][4 + j]);
            }
        }
        __syncthreads();

        // AV: q = qg*4+i, d = dg*8+.., m = ms*32+st
#pragma unroll 4
        for (int st = 0; st < 32; st++) {
            int m = ms * 32 + st;
            int slot4 = (qg ^ ((m & 63) >> 2)) << 2;
            float4 p  = *(const float4*)&sm[OFF_PT + m * 68 + slot4];
            float4 v0 = *(const float4*)&sm[OFF_VS + m * 32 + dg * 8];
            float4 v1 = *(const float4*)&sm[OFF_VS + m * 32 + dg * 8 + 4];
            u64 vp[4] = {pack2(v0.x, v0.y), pack2(v0.z, v0.w),
                         pack2(v1.x, v1.y), pack2(v1.z, v1.w)};
            float pv[4] = {p.x, p.y, p.z, p.w};
#pragma unroll
            for (int i = 0; i < 4; i++) {
                u64 pd = dup2(pv[i]);
#pragma unroll
                for (int j = 0; j < 4; j++) fma2(acc2[i][j], pd, vp[j]);
            }
        }
    }

    // row sums (16 tm threads share to; lanes are contiguous within warp)
#pragma unroll
    for (int i = 0; i < 4; i++) {
        float r = runl[i];
        r += __shfl_xor_sync(0xffffffffu, r, 8, 16);
        r += __shfl_xor_sync(0xffffffffu, r, 4, 16);
        r += __shfl_xor_sync(0xffffffffu, r, 2, 16);
        r += __shfl_xor_sync(0xffffffffu, r, 1, 16);
        if (tm == 0) sm[OFF_LR + to * 4 + i] = r;
    }
    __syncthreads();

    // park AV partials: OA[ms][q][36]
#pragma unroll
    for (int i = 0; i < 4; i++) {
        int q = qg * 4 + i;
        int base = OFF_PT + (ms * 64 + q) * 36 + dg * 8;
        float2 f0 = unpk2(acc2[i][0]), f1 = unpk2(acc2[i][1]);
        float2 f2 = unpk2(acc2[i][2]), f3 = unpk2(acc2[i][3]);
        *(float4*)&sm[base]     = make_float4(f0.x, f0.y, f1.x, f1.y);
        *(float4*)&sm[base + 4] = make_float4(f2.x, f2.y, f3.x, f3.y);
    }
    __syncthreads();
    // reduce partials -> coarse Out[q][d]
#pragma unroll
    for (int r = 0; r < 8; r++) {
        int idx = t + r * 256;
        int q = idx >> 5, d = idx & 31;
        float c = sm[OFF_PT + (0 * 64 + q) * 36 + d]
                + sm[OFF_PT + (1 * 64 + q) * 36 + d]
                + sm[OFF_PT + (2 * 64 + q) * 36 + d]
                + sm[OFF_PT + (3 * 64 + q) * 36 + d];
        sm[OFF_OUT + q * 65 + d] = c / sm[OFF_LR + q];
    }
    __syncthreads();

    // ---- fine phase, cooperative over all 256 threads ----
    // scores: thread (q = t>>2, kg = t&3) -> 4 keys; SC in KT region, stride 17
    {
        const int q = t >> 2, kg = t & 3;
        float qv[32];
#pragma unroll
        for (int d = 0; d < 32; d++) qv[d] = sm[OFF_QT + d * 68 + q];
#pragma unroll
        for (int jj = 0; jj < 4; jj++) {
            int kk = kg * 4 + jj;
            float s = 0.0f;
#pragma unroll
            for (int d = 0; d < 32; d++) s += qv[d] * sm[OFF_TK + kk * 32 + d];
            sm[OFF_KT + q * 17 + kk] = __expf(s);
        }
    }
    __syncthreads();
    if (t < 64) {
        float sum = 0.0f;
#pragma unroll
        for (int kk = 0; kk < NTK; kk++) sum += sm[OFF_KT + t * 17 + kk];
        sm[OFF_KT + t * 17 + 16] = 1.0f / sum;
    }
    __syncthreads();
    // refined: thread (q = t>>2, dq = t&3) -> 8 d
    {
        const int q = t >> 2, dq = t & 3;
        float inv = sm[OFF_KT + q * 17 + 16];
        float sc[NTK];
#pragma unroll
        for (int kk = 0; kk < NTK; kk++) sc[kk] = sm[OFF_KT + q * 17 + kk];
#pragma unroll
        for (int dd = 0; dd < 8; dd++) {
            int d = dq * 8 + dd;
            float r = 0.0f;
#pragma unroll
            for (int kk = 0; kk < NTK; kk++) r += sc[kk] * sm[OFF_TV + kk * 32 + d];
            sm[OFF_OUT + q * 65 + 32 + d] = r * inv;
        }
    }
    __syncthreads();
    // gate + combine
    {
        const int q = t >> 2, dq = t & 3;
        float g[8];
#pragma unroll
        for (int dd = 0; dd < 8; dd++) g[dd] = sm[OFF_GB + dq * 8 + dd];
        for (int c = 0; c < 64; c++) {
            float f = sm[OFF_OUT + q * 65 + c];
#pragma unroll
            for (int dd = 0; dd < 8; dd++)
                g[dd] += f * sm[OFF_GS + (dq * 8 + dd) * 64 + c];
        }
        float res[8];
#pragma unroll
        for (int dd = 0; dd < 8; dd++) {
            int d = dq * 8 + dd;
            float gv = 1.0f / (1.0f + __expf(-g[dd]));
            float cr = sm[OFF_OUT + q * 65 + d];
            float rf = sm[OFF_OUT + q * 65 + 32 + d];
            res[dd] = gv * rf + (1.0f - gv) * cr;
        }
        __syncthreads();
#pragma unroll
        for (int dd = 0; dd < 8; dd++)
            sm[OFF_OUT + q * 65 + dq * 8 + dd] = res[dd];
    }
    __syncthreads();

    // write to g_xout[b][c][n]
    float* xo = g_xout + ((long)(b * 256 + h * 32)) * NQ + n0;
#pragma unroll
    for (int r = 0; r < 8; r++) {
        int idx = t + r * 256;
        int d = idx >> 6, q = idx & 63;
        xo[(long)d * NQ + q] = sm[OFF_OUT + q * 65 + d];
    }
}

// ---------------- fused depthwise 7x7 + bilinear 2x upsample + add ----------
__global__ void __launch_bounds__(256)
dwupadd_kernel(const float* __restrict__ pe_w, const float* __restrict__ pe_b)
{
    int bc = blockIdx.x;
    int t = threadIdx.x;
    __shared__ float tile[38 * 38];
    __shared__ float wv[49];
    __shared__ float vpe[32 * 32];
    const float* src = g_vt + (long)bc * NU;
    for (int idx = t; idx < 38 * 38; idx += 256) {
        int ii = idx / 38 - 3, jj = idx % 38 - 3;
        tile[idx] = (ii >= 0 && ii < 32 && jj >= 0 && jj < 32) ? src[ii * 32 + jj] : 0.0f;
    }
    int c = bc & 255;
    if (t < 49) wv[t] = pe_w[c * 49 + t];
    __syncthreads();
    float bias = pe_b[c];
    for (int idx = t; idx < NU; idx += 256) {
        int i = idx >> 5, j = idx & 31;
        float s = bias;
#pragma unroll
        for (int di = 0; di < 7; di++)
#pragma unroll
            for (int dj = 0; dj < 7; dj++)
                s += tile[(i + di) * 38 + (j + dj)] * wv[di * 7 + dj];
        vpe[idx] = s;
    }
    __syncthreads();
    float* xo = g_xout + (long)bc * NQ;
    for (int idx = t; idx < NQ; idx += 256) {
        int I = idx >> 6, J = idx & 63;
        int i0, i1, j0, j1; float wi0, wi1, wj0, wj1;
        if (I & 1) { i0 = I >> 1; wi0 = 0.75f; i1 = min(i0 + 1, 31); wi1 = 0.25f; }
        else       { i1 = I >> 1; wi1 = 0.75f; i0 = max(i1 - 1, 0);  wi0 = 0.25f; }
        if (J & 1) { j0 = J >> 1; wj0 = 0.75f; j1 = min(j0 + 1, 31); wj1 = 0.25f; }
        else       { j1 = J >> 1; wj1 = 0.75f; j0 = max(j1 - 1, 0);  wj0 = 0.25f; }
        float val = wi0 * (wj0 * vpe[i0 * 32 + j0] + wj1 * vpe[i0 * 32 + j1])
                  + wi1 * (wj0 * vpe[i1 * 32 + j0] + wj1 * vpe[i1 * 32 + j1]);
        xo[idx] += val;
    }
}

// ---------------- launch -----------------------------------------------------
extern "C" void kernel_launch(void* const* d_in, const int* in_sizes, int n_in,
                              void* d_out, int out_size)
{
    const float* x      = (const float*)d_in[0];
    const float* upper  = (const float*)d_in[1];
    const float* q_w    = (const float*)d_in[2];
    const float* q_b    = (const float*)d_in[3];
    const float* kv_w   = (const float*)d_in[4];
    const float* kv_b   = (const float*)d_in[5];
    const float* proj_w = (const float*)d_in[6];
    const float* proj_b = (const float*)d_in[7];
    const float* pe_w   = (const float*)d_in[8];
    const float* pe_b   = (const float*)d_in[9];
    const float* gate_w = (const float*)d_in[10];
    const float* gate_b = (const float*)d_in[11];
    float* out = (float*)d_out;

    cudaFuncSetAttribute(attn_kernel, cudaFuncAttributeMaxDynamicSharedMemorySize,
                         ATTN_SMEM_FLOATS * 4);

    gemm_kernel<<<dim3(32, 6, 2), 256>>>(x, q_w, q_b, kv_w, kv_b, nullptr, NQ, 0);
    gemm_kernel<<<dim3(8, 4, 2), 256>>>(upper, kv_w, kv_b, nullptr, nullptr, nullptr, NU, 1);
    topk_kernel<<<16, 256>>>();
    attn_kernel<<<dim3(64, 16), 256, ATTN_SMEM_FLOATS * 4>>>(gate_w, gate_b);
    dwupadd_kernel<<<BATCH * DIM, 256>>>(pe_w, pe_b);
    gemm_kernel<<<dim3(32, 2, 2), 256>>>(nullptr, proj_w, proj_b, nullptr, nullptr, out, NQ, 2);
}

// round 7
// speedup vs baseline: 1.2794x; 1.0013x over previous
#include <cuda_runtime.h>
#include <math.h>
#include <stdint.h>

#define BATCH 2
#define DIM 256
#define HEADS 8
#define HD 32
#define NQ 4096
#define NU 1024
#define TOPK 4
#define NTK 16
#define ATT_SCALE 0.17677669529663687f  // 32^-0.5

typedef unsigned long long u64;

// ---------------- f32x2 packed math (sm_103a) --------------------------------
__device__ __forceinline__ u64 pack2(float a, float b) {
    u64 r; asm("mov.b64 %0, {%1, %2};" : "=l"(r) : "f"(a), "f"(b)); return r;
}
__device__ __forceinline__ u64 dup2(float a) {
    u64 r; asm("mov.b64 %0, {%1, %1};" : "=l"(r) : "f"(a)); return r;
}
__device__ __forceinline__ void fma2(u64& d, u64 a, u64 b) {
    asm("fma.rn.f32x2 %0, %1, %2, %3;" : "=l"(d) : "l"(a), "l"(b), "l"(d));
}
__device__ __forceinline__ float2 unpk2(u64 v) {
    float2 r; asm("mov.b64 {%0, %1}, %2;" : "=f"(r.x), "=f"(r.y) : "l"(v)); return r;
}

// ---------------- scratch (static __device__, no allocation) ----------------
__device__ float g_qT [BATCH*HEADS*HD*NQ];   // pre-scaled by ATT_SCALE
__device__ float g_fkT[BATCH*HEADS*HD*NQ];
__device__ float g_fvT[BATCH*HEADS*HD*NQ];
__device__ float g_kT [BATCH*HEADS*HD*NU];
__device__ float g_v  [BATCH*HEADS*NU*HD];   // [bh][m][d]
__device__ float g_vt [BATCH*DIM*NU];        // [b][c][m]
__device__ float g_xout[BATCH*DIM*NQ];       // [b][c][n]
__device__ int   g_txi[16*NTK];

// ---------------- threefry2x32, JAX partitionable path, key=(0,42) ----------
__device__ __forceinline__ void threefry2x32_k42(uint32_t x0, uint32_t x1,
                                                 uint32_t& o0, uint32_t& o1) {
    const uint32_t ks0 = 0u, ks1 = 42u, ks2 = 0u ^ 42u ^ 0x1BD11BDAu;
    x0 += ks0; x1 += ks1;
#define TF_R(r) { x0 += x1; x1 = (x1 << (r)) | (x1 >> (32 - (r))); x1 ^= x0; }
    TF_R(13) TF_R(15) TF_R(26) TF_R(6)
    x0 += ks1; x1 += ks2 + 1u;
    TF_R(17) TF_R(29) TF_R(16) TF_R(24)
    x0 += ks2; x1 += ks0 + 2u;
    TF_R(13) TF_R(15) TF_R(26) TF_R(6)
    x0 += ks0; x1 += ks1 + 3u;
    TF_R(17) TF_R(29) TF_R(16) TF_R(24)
    x0 += ks1; x1 += ks2 + 4u;
    TF_R(13) TF_R(15) TF_R(26) TF_R(6)
    x0 += ks2; x1 += ks0 + 5u;
#undef TF_R
    o0 = x0; o1 = x1;
}

__device__ __forceinline__ float gumbel_at(uint32_t l) {
    uint32_t o0, o1;
    threefry2x32_k42(0u, l, o0, o1);
    uint32_t bits = o0 ^ o1;
    uint32_t fb = (bits >> 9) | 0x3F800000u;
    float u01 = __uint_as_float(fb) - 1.0f;
    const float TINY = 1.17549435e-38f;
    float u = u01 * (1.0f - TINY) + TINY;
    u = fmaxf(TINY, u);
    return -logf(-logf(u));
}

// ---------------- GEMM: out[o][p] = sum_c X[c][p] W[o][c] + bias ------------
// 128x128 tile, 8x8 microtile with f32x2 packed FMA, double-buffered smem.
__global__ void __launch_bounds__(256, 2)
gemm_kernel(const float* __restrict__ X,
            const float* __restrict__ W1, const float* __restrict__ B1,
            const float* __restrict__ W2, const float* __restrict__ B2,
            float* __restrict__ dst, int P, int mode)
{
    __shared__ float Xs[2][8][128];
    __shared__ float Wt[2][8][132];
    const int b  = blockIdx.z;
    const int p0 = blockIdx.x * 128;
    const int o0 = blockIdx.y * 128;
    const int t  = threadIdx.x;
    const int to = t >> 4;
    const int tp = t & 15;

    const int xc  = t >> 5, xp4 = t & 31;
    const int woo = t >> 1, whalf = t & 1;

    const float* Xb = (mode == 2) ? (g_xout + (long)b * DIM * P)
                                  : (X + (long)b * DIM * P);
    int ow = o0 + woo;
    const float* wptr;
    if (mode == 0 && ow >= 256) wptr = W2 + (ow - 256) * DIM;
    else                        wptr = W1 + ow * DIM;

    float4 xr = *(const float4*)&Xb[(long)xc * P + p0 + xp4 * 4];
    float4 wr = *(const float4*)&wptr[whalf * 4];

    u64 acc2[8][4];
#pragma unroll
    for (int i = 0; i < 8; i++)
#pragma unroll
        for (int j = 0; j < 4; j++) acc2[i][j] = 0ULL;

    int buf = 0;
    for (int c0 = 0; c0 < DIM; c0 += 8) {
        *(float4*)&Xs[buf][xc][xp4 * 4] = xr;
        Wt[buf][whalf * 4 + 0][woo] = wr.x;
        Wt[buf][whalf * 4 + 1][woo] = wr.y;
        Wt[buf][whalf * 4 + 2][woo] = wr.z;
        Wt[buf][whalf * 4 + 3][woo] = wr.w;
        __syncthreads();
        if (c0 + 8 < DIM) {
            xr = *(const float4*)&Xb[(long)(c0 + 8 + xc) * P + p0 + xp4 * 4];
            wr = *(const float4*)&wptr[c0 + 8 + whalf * 4];
        }
#pragma unroll
        for (int k = 0; k < 8; k++) {
            float4 a0 = *(const float4*)&Wt[buf][k][to * 8];
            float4 a1 = *(const float4*)&Wt[buf][k][to * 8 + 4];
            float4 x0 = *(const float4*)&Xs[buf][k][tp * 8];
            float4 x1 = *(const float4*)&Xs[buf][k][tp * 8 + 4];
            u64 xp[4] = {pack2(x0.x, x0.y), pack2(x0.z, x0.w),
                         pack2(x1.x, x1.y), pack2(x1.z, x1.w)};
            float av[8] = {a0.x, a0.y, a0.z, a0.w, a1.x, a1.y, a1.z, a1.w};
#pragma unroll
            for (int i = 0; i < 8; i++) {
                u64 ad = dup2(av[i]);
#pragma unroll
                for (int j = 0; j < 4; j++) fma2(acc2[i][j], ad, xp[j]);
            }
        }
        buf ^= 1;
    }

    const int p = p0 + tp * 8;
#pragma unroll
    for (int i = 0; i < 8; i++) {
        int o = o0 + to * 8 + i;
        float bias = (mode == 0 && o >= 256) ? B2[o - 256] : B1[o];
        float r[8];
#pragma unroll
        for (int j = 0; j < 4; j++) {
            float2 f = unpk2(acc2[i][j]);
            r[j * 2] = f.x + bias; r[j * 2 + 1] = f.y + bias;
        }
        if (mode == 0) {
            if (o < 256) {
#pragma unroll
                for (int j = 0; j < 8; j++) r[j] *= ATT_SCALE;
                float* ptr = g_qT + ((long)(b * 8 + (o >> 5)) * 32 + (o & 31)) * NQ + p;
                *(float4*)&ptr[0] = make_float4(r[0], r[1], r[2], r[3]);
                *(float4*)&ptr[4] = make_float4(r[4], r[5], r[6], r[7]);
            } else {
                int e2 = o - 256, h = e2 >> 6, e = e2 & 63;
                float* base = (e < 32) ? g_fkT : g_fvT;
                float* ptr = base + ((long)(b * 8 + h) * 32 + (e & 31)) * NQ + p;
                *(float4*)&ptr[0] = make_float4(r[0], r[1], r[2], r[3]);
                *(float4*)&ptr[4] = make_float4(r[4], r[5], r[6], r[7]);
            }
        } else if (mode == 1) {
            int h = o >> 6, e = o & 63;
            if (e < 32) {
                float* ptr = g_kT + ((long)(b * 8 + h) * 32 + e) * NU + p;
                *(float4*)&ptr[0] = make_float4(r[0], r[1], r[2], r[3]);
                *(float4*)&ptr[4] = make_float4(r[4], r[5], r[6], r[7]);
            } else {
                int d = e - 32;
#pragma unroll
                for (int j = 0; j < 8; j++)
                    g_v[((long)(b * 8 + h) * NU + p + j) * 32 + d] = r[j];
                float* ptr = g_vt + ((long)(b * 256 + h * 32 + d)) * NU + p;
                *(float4*)&ptr[0] = make_float4(r[0], r[1], r[2], r[3]);
                *(float4*)&ptr[4] = make_float4(r[4], r[5], r[6], r[7]);
            }
        } else {
            float* ptr = dst + ((long)(b * 256 + o)) * NQ + p;
            *(float4*)&ptr[0] = make_float4(r[0], r[1], r[2], r[3]);
            *(float4*)&ptr[4] = make_float4(r[4], r[5], r[6], r[7]);
        }
    }
}

// ---------------- fused qmean + gsim + gumbel + top4 + txi ------------------
__global__ void __launch_bounds__(256) topk_kernel() {
    const int bh = blockIdx.x;
    const int t = threadIdx.x;
    const int w = t >> 5, l = t & 31;
    __shared__ float qm[32];
    __shared__ float cv[32];
    __shared__ int   ci[32];
    __shared__ int   sel[TOPK];

    const float* qb = g_qT + (long)bh * 32 * NQ;
#pragma unroll
    for (int dd = 0; dd < 4; dd++) {
        int d = w * 4 + dd;
        float s = 0.0f;
        const float* row = qb + (long)d * NQ;
        for (int i = l; i < NQ; i += 32) s += row[i];
#pragma unroll
        for (int off = 16; off >= 1; off >>= 1)
            s += __shfl_xor_sync(0xffffffffu, s, off);
        if (l == 0) qm[d] = s * (1.0f / (float)NQ);
    }
    __syncthreads();

    const float* kb = g_kT + (long)bh * 32 * NU;
    float v[4]; int id[4];
#pragma unroll
    for (int r = 0; r < 4; r++) {
        int m = t + r * 256;
        float s = 0.0f;
#pragma unroll
        for (int d = 0; d < 32; d++) s += qm[d] * kb[d * NU + m];
        v[r] = s + gumbel_at((uint32_t)(bh * NU + m));
        id[r] = m;
    }

#pragma unroll
    for (int it = 0; it < TOPK; it++) {
        float lv = v[0]; int li = id[0];
#pragma unroll
        for (int r = 1; r < 4; r++) if (v[r] > lv) { lv = v[r]; li = id[r]; }
#pragma unroll
        for (int off = 16; off >= 1; off >>= 1) {
            float ov = __shfl_xor_sync(0xffffffffu, lv, off);
            int   oi = __shfl_xor_sync(0xffffffffu, li, off);
            if (ov > lv) { lv = ov; li = oi; }
        }
#pragma unroll
        for (int r = 0; r < 4; r++) if (id[r] == li) v[r] = -INFINITY;
        if (l == 0) { cv[w * 4 + it] = lv; ci[w * 4 + it] = li; }
    }
    __syncthreads();

    if (t < 32) {
        float lv = cv[t]; int li = ci[t];
#pragma unroll
        for (int it = 0; it < TOPK; it++) {
            float bv = lv; int bi = li;
#pragma unroll
            for (int off = 16; off >= 1; off >>= 1) {
                float ov = __shfl_xor_sync(0xffffffffu, bv, off);
                int   oi = __shfl_xor_sync(0xffffffffu, bi, off);
                if (ov > bv) { bv = ov; bi = oi; }
            }
            if (li == bi) lv = -INFINITY;
            if (t == 0) sel[it] = bi;
        }
    }
    __syncthreads();

    if (t < NTK) {
        int grp = t / TOPK, kk = t % TOPK;
        int dh = grp >> 1, dw = grp & 1;
        int m = sel[kk];
        int hi = (m >> 5) * 2, wi = (m & 31) * 2;
        g_txi[bh * NTK + t] = (hi + dh) * 64 + (wi + dw);
    }
}

// ---------------- fused attention (q-block 64, f32x2, 2 blocks/SM) ---------
#define OFF_QT  0        // [32][68]
#define OFF_KT  2176     // [32][132]   (reused as SC[64][17] in fine phase)
#define OFF_VS  6400     // [128][32]
#define OFF_PT  10496    // P: [128][68] (8704) / OA: [4][64][36] (9216)
#define OFF_LR  19712    // [64]
#define OFF_OUT 19776    // [64][65]
#define OFF_TK  23936    // [16][32]
#define OFF_TV  24448    // [16][32]
#define OFF_GS  24960    // [32][64]
#define OFF_GB  27008    // [32]
#define OFF_TXI 27040    // int[16]
#define ATTN_SMEM_FLOATS 27056

__global__ void __launch_bounds__(256, 2)
attn_kernel(const float* __restrict__ gate_w, const float* __restrict__ gate_b)
{
    extern __shared__ float sm[];
    const int bh = blockIdx.y;
    const int n0 = blockIdx.x * 64;
    const int t  = threadIdx.x;
    const int b = bh >> 3, h = bh & 7;
    const int to = t >> 4, tm = t & 15;                       // QK: 4q x (4+4)m
    const int ms = t >> 6, dg = (t >> 4) & 3, qg = t & 15;    // AV: 4q x 8d, 4-way m

    // prologue
    const float* qb = g_qT + (long)bh * 32 * NQ + n0;
#pragma unroll
    for (int r = 0; r < 2; r++) {
        int f4 = t + r * 256;            // 512 f4 = 32 d x 16
        int d = f4 >> 4, qf = (f4 & 15) << 2;
        *(float4*)&sm[OFF_QT + d * 68 + qf] = *(const float4*)&qb[(long)d * NQ + qf];
    }
#pragma unroll
    for (int r = 0; r < 8; r++) sm[OFF_GS + t + r * 256] = gate_w[t + r * 256];
    if (t < 32) sm[OFF_GB + t] = gate_b[t];
    if (t < NTK) ((int*)sm)[OFF_TXI + t] = g_txi[bh * NTK + t];
    __syncthreads();
#pragma unroll
    for (int r = 0; r < 2; r++) {
        int idx = t + r * 256;
        int kk = idx >> 5, d = idx & 31;
        int m = ((int*)sm)[OFF_TXI + kk];
        sm[OFF_TK + kk * 32 + d] = g_fkT[((long)bh * 32 + d) * NQ + m];
        sm[OFF_TV + kk * 32 + d] = g_fvT[((long)bh * 32 + d) * NQ + m];
    }

    u64 acc2[4][4];
    float runl[4];
#pragma unroll
    for (int i = 0; i < 4; i++) {
        runl[i] = 0.0f;
#pragma unroll
        for (int j = 0; j < 4; j++) acc2[i][j] = 0ULL;
    }

    const float* kb = g_kT + (long)bh * 32 * NU;
    const float* vb = g_v  + (long)bh * NU * 32;

    for (int m0 = 0; m0 < NU; m0 += 128) {
        __syncthreads();
        // stage K^T [32][128] and V [128][32]
#pragma unroll
        for (int r = 0; r < 4; r++) {
            int f4 = t + r * 256;        // 1024 f4
            int d = f4 >> 5, mf = (f4 & 31) << 2;
            *(float4*)&sm[OFF_KT + d * 132 + mf] =
                *(const float4*)&kb[(long)d * NU + m0 + mf];
            *(float4*)&sm[OFF_VS + f4 * 4] =
                *(const float4*)&vb[(long)m0 * 32 + f4 * 4];
        }
        __syncthreads();

        // QK: q = to*4+i, m = tm*4+{0..3} and 64+tm*4+{0..3}
        u64 s2[4][4];
#pragma unroll
        for (int i = 0; i < 4; i++)
#pragma unroll
            for (int j = 0; j < 4; j++) s2[i][j] = 0ULL;
#pragma unroll 4
        for (int k = 0; k < 32; k++) {
            float4 a  = *(const float4*)&sm[OFF_QT + k * 68 + to * 4];
            float4 b0 = *(const float4*)&sm[OFF_KT + k * 132 + tm * 4];
            float4 b1 = *(const float4*)&sm[OFF_KT + k * 132 + tm * 4 + 64];
            u64 bp[4] = {pack2(b0.x, b0.y), pack2(b0.z, b0.w),
                         pack2(b1.x, b1.y), pack2(b1.z, b1.w)};
            float av[4] = {a.x, a.y, a.z, a.w};
#pragma unroll
            for (int i = 0; i < 4; i++) {
                u64 ad = dup2(av[i]);
#pragma unroll
                for (int j = 0; j < 4; j++) fma2(s2[i][j], ad, bp[j]);
            }
        }
        // exp + partial row sums
        float e[4][8];
#pragma unroll
        for (int i = 0; i < 4; i++) {
#pragma unroll
            for (int j = 0; j < 4; j++) {
                float2 f = unpk2(s2[i][j]);
                e[i][j * 2]     = __expf(f.x);
                e[i][j * 2 + 1] = __expf(f.y);
                runl[i] += e[i][j * 2] + e[i][j * 2 + 1];
            }
        }
        // transposed store: PT[m][slot], slot = to ^ tm (optimal 4-wf)
        {
            int slot4 = (to ^ tm) << 2;
#pragma unroll
            for (int j = 0; j < 4; j++) {
                int m = tm * 4 + j;
                *(float4*)&sm[OFF_PT + m * 68 + slot4] =
                    make_float4(e[0][j], e[1][j], e[2][j], e[3][j]);
            }
#pragma unroll
            for (int j = 0; j < 4; j++) {
                int m = 64 + tm * 4 + j;
                *(float4*)&sm[OFF_PT + m * 68 + slot4] =
                    make_float4(e[0][4 + j], e[1][4 + j], e[2][4 + j], e[3][4 + j]);
            }
        }
        __syncthreads();

        // AV: q = qg*4+i, d = dg*8+.., m = ms*32+st
#pragma unroll 4
        for (int st = 0; st < 32; st++) {
            int m = ms * 32 + st;
            int slot4 = (qg ^ ((m & 63) >> 2)) << 2;
            float4 p  = *(const float4*)&sm[OFF_PT + m * 68 + slot4];
            float4 v0 = *(const float4*)&sm[OFF_VS + m * 32 + dg * 8];
            float4 v1 = *(const float4*)&sm[OFF_VS + m * 32 + dg * 8 + 4];
            u64 vp[4] = {pack2(v0.x, v0.y), pack2(v0.z, v0.w),
                         pack2(v1.x, v1.y), pack2(v1.z, v1.w)};
            float pv[4] = {p.x, p.y, p.z, p.w};
#pragma unroll
            for (int i = 0; i < 4; i++) {
                u64 pd = dup2(pv[i]);
#pragma unroll
                for (int j = 0; j < 4; j++) fma2(acc2[i][j], pd, vp[j]);
            }
        }
    }

    // row sums (16 tm threads share to; lanes are contiguous within warp)
#pragma unroll
    for (int i = 0; i < 4; i++) {
        float r = runl[i];
        r += __shfl_xor_sync(0xffffffffu, r, 8, 16);
        r += __shfl_xor_sync(0xffffffffu, r, 4, 16);
        r += __shfl_xor_sync(0xffffffffu, r, 2, 16);
        r += __shfl_xor_sync(0xffffffffu, r, 1, 16);
        if (tm == 0) sm[OFF_LR + to * 4 + i] = r;
    }
    __syncthreads();

    // park AV partials: OA[ms][q][36]
#pragma unroll
    for (int i = 0; i < 4; i++) {
        int q = qg * 4 + i;
        int base = OFF_PT + (ms * 64 + q) * 36 + dg * 8;
        float2 f0 = unpk2(acc2[i][0]), f1 = unpk2(acc2[i][1]);
        float2 f2 = unpk2(acc2[i][2]), f3 = unpk2(acc2[i][3]);
        *(float4*)&sm[base]     = make_float4(f0.x, f0.y, f1.x, f1.y);
        *(float4*)&sm[base + 4] = make_float4(f2.x, f2.y, f3.x, f3.y);
    }
    __syncthreads();
    // reduce partials -> coarse Out[q][d]
#pragma unroll
    for (int r = 0; r < 8; r++) {
        int idx = t + r * 256;
        int q = idx >> 5, d = idx & 31;
        float c = sm[OFF_PT + (0 * 64 + q) * 36 + d]
                + sm[OFF_PT + (1 * 64 + q) * 36 + d]
                + sm[OFF_PT + (2 * 64 + q) * 36 + d]
                + sm[OFF_PT + (3 * 64 + q) * 36 + d];
        sm[OFF_OUT + q * 65 + d] = c / sm[OFF_LR + q];
    }
    __syncthreads();

    // ---- fine phase, cooperative over all 256 threads ----
    // scores: thread (q = t>>2, kg = t&3) -> 4 keys; SC in KT region, stride 17
    {
        const int q = t >> 2, kg = t & 3;
        float qv[32];
#pragma unroll
        for (int d = 0; d < 32; d++) qv[d] = sm[OFF_QT + d * 68 + q];
#pragma unroll
        for (int jj = 0; jj < 4; jj++) {
            int kk = kg * 4 + jj;
            float s = 0.0f;
#pragma unroll
            for (int d = 0; d < 32; d++) s += qv[d] * sm[OFF_TK + kk * 32 + d];
            sm[OFF_KT + q * 17 + kk] = __expf(s);
        }
    }
    __syncthreads();
    if (t < 64) {
        float sum = 0.0f;
#pragma unroll
        for (int kk = 0; kk < NTK; kk++) sum += sm[OFF_KT + t * 17 + kk];
        sm[OFF_KT + t * 17 + 16] = 1.0f / sum;
    }
    __syncthreads();
    // refined: thread (q = t>>2, dq = t&3) -> 8 d
    {
        const int q = t >> 2, dq = t & 3;
        float inv = sm[OFF_KT + q * 17 + 16];
        float sc[NTK];
#pragma unroll
        for (int kk = 0; kk < NTK; kk++) sc[kk] = sm[OFF_KT + q * 17 + kk];
#pragma unroll
        for (int dd = 0; dd < 8; dd++) {
            int d = dq * 8 + dd;
            float r = 0.0f;
#pragma unroll
            for (int kk = 0; kk < NTK; kk++) r += sc[kk] * sm[OFF_TV + kk * 32 + d];
            sm[OFF_OUT + q * 65 + 32 + d] = r * inv;
        }
    }
    __syncthreads();
    // gate + combine
    {
        const int q = t >> 2, dq = t & 3;
        float g[8];
#pragma unroll
        for (int dd = 0; dd < 8; dd++) g[dd] = sm[OFF_GB + dq * 8 + dd];
        for (int c = 0; c < 64; c++) {
            float f = sm[OFF_OUT + q * 65 + c];
#pragma unroll
            for (int dd = 0; dd < 8; dd++)
                g[dd] += f * sm[OFF_GS + (dq * 8 + dd) * 64 + c];
        }
        float res[8];
#pragma unroll
        for (int dd = 0; dd < 8; dd++) {
            int d = dq * 8 + dd;
            float gv = 1.0f / (1.0f + __expf(-g[dd]));
            float cr = sm[OFF_OUT + q * 65 + d];
            float rf = sm[OFF_OUT + q * 65 + 32 + d];
            res[dd] = gv * rf + (1.0f - gv) * cr;
        }
        __syncthreads();
#pragma unroll
        for (int dd = 0; dd < 8; dd++)
            sm[OFF_OUT + q * 65 + dq * 8 + dd] = res[dd];
    }
    __syncthreads();

    // write to g_xout[b][c][n]
    float* xo = g_xout + ((long)(b * 256 + h * 32)) * NQ + n0;
#pragma unroll
    for (int r = 0; r < 8; r++) {
        int idx = t + r * 256;
        int d = idx >> 6, q = idx & 63;
        xo[(long)d * NQ + q] = sm[OFF_OUT + q * 65 + d];
    }
}

// ---------------- fused depthwise 7x7 + bilinear 2x upsample + add ----------
__global__ void __launch_bounds__(256)
dwupadd_kernel(const float* __restrict__ pe_w, const float* __restrict__ pe_b)
{
    int bc = blockIdx.x;
    int t = threadIdx.x;
    __shared__ float tile[38 * 38];
    __shared__ float wv[49];
    __shared__ float vpe[32 * 32];
    const float* src = g_vt + (long)bc * NU;
    for (int idx = t; idx < 38 * 38; idx += 256) {
        int ii = idx / 38 - 3, jj = idx % 38 - 3;
        tile[idx] = (ii >= 0 && ii < 32 && jj >= 0 && jj < 32) ? src[ii * 32 + jj] : 0.0f;
    }
    int c = bc & 255;
    if (t < 49) wv[t] = pe_w[c * 49 + t];
    __syncthreads();
    float bias = pe_b[c];
    for (int idx = t; idx < NU; idx += 256) {
        int i = idx >> 5, j = idx & 31;
        float s = bias;
#pragma unroll
        for (int di = 0; di < 7; di++)
#pragma unroll
            for (int dj = 0; dj < 7; dj++)
                s += tile[(i + di) * 38 + (j + dj)] * wv[di * 7 + dj];
        vpe[idx] = s;
    }
    __syncthreads();
    float* xo = g_xout + (long)bc * NQ;
    for (int idx = t; idx < NQ; idx += 256) {
        int I = idx >> 6, J = idx & 63;
        int i0, i1, j0, j1; float wi0, wi1, wj0, wj1;
        if (I & 1) { i0 = I >> 1; wi0 = 0.75f; i1 = min(i0 + 1, 31); wi1 = 0.25f; }
        else       { i1 = I >> 1; wi1 = 0.75f; i0 = max(i1 - 1, 0);  wi0 = 0.25f; }
        if (J & 1) { j0 = J >> 1; wj0 = 0.75f; j1 = min(j0 + 1, 31); wj1 = 0.25f; }
        else       { j1 = J >> 1; wj1 = 0.75f; j0 = max(j1 - 1, 0);  wj0 = 0.25f; }
        float val = wi0 * (wj0 * vpe[i0 * 32 + j0] + wj1 * vpe[i0 * 32 + j1])
                  + wi1 * (wj0 * vpe[i1 * 32 + j0] + wj1 * vpe[i1 * 32 + j1]);
        xo[idx] += val;
    }
}

// ---------------- launch -----------------------------------------------------
extern "C" void kernel_launch(void* const* d_in, const int* in_sizes, int n_in,
                              void* d_out, int out_size)
{
    const float* x      = (const float*)d_in[0];
    const float* upper  = (const float*)d_in[1];
    const float* q_w    = (const float*)d_in[2];
    const float* q_b    = (const float*)d_in[3];
    const float* kv_w   = (const float*)d_in[4];
    const float* kv_b   = (const float*)d_in[5];
    const float* proj_w = (const float*)d_in[6];
    const float* proj_b = (const float*)d_in[7];
    const float* pe_w   = (const float*)d_in[8];
    const float* pe_b   = (const float*)d_in[9];
    const float* gate_w = (const float*)d_in[10];
    const float* gate_b = (const float*)d_in[11];
    float* out = (float*)d_out;

    cudaFuncSetAttribute(attn_kernel, cudaFuncAttributeMaxDynamicSharedMemorySize,
                         ATTN_SMEM_FLOATS * 4);

    gemm_kernel<<<dim3(32, 6, 2), 256>>>(x, q_w, q_b, kv_w, kv_b, nullptr, NQ, 0);
    gemm_kernel<<<dim3(8, 4, 2), 256>>>(upper, kv_w, kv_b, nullptr, nullptr, nullptr, NU, 1);
    topk_kernel<<<16, 256>>>();
    attn_kernel<<<dim3(64, 16), 256, ATTN_SMEM_FLOATS * 4>>>(gate_w, gate_b);
    dwupadd_kernel<<<BATCH * DIM, 256>>>(pe_w, pe_b);
    gemm_kernel<<<dim3(32, 2, 2), 256>>>(nullptr, proj_w, proj_b, nullptr, nullptr, out, NQ, 2);
}

// round 8
// speedup vs baseline: 1.3810x; 1.0794x over previous
#include <cuda_runtime.h>
#include <math.h>
#include <stdint.h>

#define BATCH 2
#define DIM 256
#define HEADS 8
#define NQ 4096
#define NU 1024
#define TOPK 4
#define NTK 16
#define ATT_SCALE 0.17677669529663687f

typedef unsigned long long u64;

__device__ __forceinline__ u64 dup2(float a) {
    u64 r; asm("mov.b64 %0, {%1, %1};" : "=l"(r) : "f"(a)); return r;
}
__device__ __forceinline__ void fma2(u64& d, u64 a, u64 b) {
    asm("fma.rn.f32x2 %0, %1, %2, %3;" : "=l"(d) : "l"(a), "l"(b), "l"(d));
}
__device__ __forceinline__ float2 unpk2(u64 v) {
    float2 r; asm("mov.b64 {%0, %1}, %2;" : "=f"(r.x), "=f"(r.y) : "l"(v)); return r;
}

__device__ float g_qT [BATCH*HEADS*32*NQ];
__device__ float g_fkT[BATCH*HEADS*32*NQ];
__device__ float g_fvT[BATCH*HEADS*32*NQ];
__device__ float g_kT [BATCH*HEADS*32*NU];
__device__ float g_v  [BATCH*HEADS*NU*32];
__device__ float g_vt [BATCH*DIM*NU];
__device__ float g_xout[BATCH*DIM*NQ];
__device__ int   g_txi[16*NTK];

__device__ __forceinline__ void threefry2x32_k42(uint32_t x0, uint32_t x1,
                                                 uint32_t& o0, uint32_t& o1) {
    const uint32_t ks1 = 42u, ks2 = 42u ^ 0x1BD11BDAu;
    x1 += ks1;
#define TF_R(r) { x0 += x1; x1 = (x1 << (r)) | (x1 >> (32 - (r))); x1 ^= x0; }
    TF_R(13) TF_R(15) TF_R(26) TF_R(6)
    x0 += ks1; x1 += ks2 + 1u;
    TF_R(17) TF_R(29) TF_R(16) TF_R(24)
    x0 += ks2; x1 += 2u;
    TF_R(13) TF_R(15) TF_R(26) TF_R(6)
    x0 += 0u; x1 += ks1 + 3u;
    TF_R(17) TF_R(29) TF_R(16) TF_R(24)
    x0 += ks1; x1 += ks2 + 4u;
    TF_R(13) TF_R(15) TF_R(26) TF_R(6)
    x0 += ks2; x1 += 5u;
#undef TF_R
    o0 = x0; o1 = x1;
}

__device__ __forceinline__ float gumbel_at(uint32_t l) {
    uint32_t o0, o1;
    threefry2x32_k42(0u, l, o0, o1);
    uint32_t bits = o0 ^ o1;
    float u01 = __uint_as_float((bits >> 9) | 0x3F800000u) - 1.0f;
    const float TINY = 1.17549435e-38f;
    float u = fmaxf(TINY, u01 * (1.0f - TINY) + TINY);
    return -logf(-logf(u));
}

// ---------------- GEMM 128x128, 8x8 microtile, f32x2 ------------------------
__global__ void __launch_bounds__(256, 2)
gemm_kernel(const float* __restrict__ X,
            const float* __restrict__ W1, const float* __restrict__ B1,
            const float* __restrict__ W2, const float* __restrict__ B2,
            float* __restrict__ dst, int P, int mode)
{
    __shared__ float Xs[2][8][128];
    __shared__ float Wt[2][8][132];
    const int b = blockIdx.z, p0 = blockIdx.x * 128, o0 = blockIdx.y * 128;
    const int t = threadIdx.x, to = t >> 4, tp = t & 15;
    const int xc = t >> 5, xp4 = t & 31, woo = t >> 1, whalf = t & 1;

    const float* Xb = (mode == 2) ? (g_xout + (long)b * DIM * P) : (X + (long)b * DIM * P);
    int ow = o0 + woo;
    const float* wptr = (mode == 0 && ow >= 256) ? W2 + (ow - 256) * DIM : W1 + ow * DIM;

    float4 xr = *(const float4*)&Xb[(long)xc * P + p0 + xp4 * 4];
    float4 wr = *(const float4*)&wptr[whalf * 4];

    u64 acc2[8][4];
#pragma unroll
    for (int i = 0; i < 8; i++)
#pragma unroll
        for (int j = 0; j < 4; j++) acc2[i][j] = 0ULL;

    int buf = 0;
    for (int c0 = 0; c0 < DIM; c0 += 8) {
        *(float4*)&Xs[buf][xc][xp4 * 4] = xr;
        Wt[buf][whalf * 4 + 0][woo] = wr.x;
        Wt[buf][whalf * 4 + 1][woo] = wr.y;
        Wt[buf][whalf * 4 + 2][woo] = wr.z;
        Wt[buf][whalf * 4 + 3][woo] = wr.w;
        __syncthreads();
        if (c0 + 8 < DIM) {
            xr = *(const float4*)&Xb[(long)(c0 + 8 + xc) * P + p0 + xp4 * 4];
            wr = *(const float4*)&wptr[c0 + 8 + whalf * 4];
        }
#pragma unroll
        for (int k = 0; k < 8; k++) {
            float4 a0 = *(const float4*)&Wt[buf][k][to * 8];
            float4 a1 = *(const float4*)&Wt[buf][k][to * 8 + 4];
            ulonglong2 xl = *(const ulonglong2*)&Xs[buf][k][tp * 8];
            ulonglong2 xh = *(const ulonglong2*)&Xs[buf][k][tp * 8 + 4];
            u64 xp[4] = {xl.x, xl.y, xh.x, xh.y};
            float av[8] = {a0.x, a0.y, a0.z, a0.w, a1.x, a1.y, a1.z, a1.w};
#pragma unroll
            for (int i = 0; i < 8; i++) {
                u64 ad = dup2(av[i]);
#pragma unroll
                for (int j = 0; j < 4; j++) fma2(acc2[i][j], ad, xp[j]);
            }
        }
        buf ^= 1;
    }

    const int p = p0 + tp * 8;
#pragma unroll
    for (int i = 0; i < 8; i++) {
        int o = o0 + to * 8 + i;
        float bias = (mode == 0 && o >= 256) ? B2[o - 256] : B1[o];
        float r[8];
#pragma unroll
        for (int j = 0; j < 4; j++) {
            float2 f = unpk2(acc2[i][j]);
            r[j * 2] = f.x + bias; r[j * 2 + 1] = f.y + bias;
        }
        if (mode == 0) {
            if (o < 256) {
#pragma unroll
                for (int j = 0; j < 8; j++) r[j] *= ATT_SCALE;
                float* ptr = g_qT + ((long)(b * 8 + (o >> 5)) * 32 + (o & 31)) * NQ + p;
                *(float4*)&ptr[0] = make_float4(r[0], r[1], r[2], r[3]);
                *(float4*)&ptr[4] = make_float4(r[4], r[5], r[6], r[7]);
            } else {
                int e2 = o - 256, h = e2 >> 6, e = e2 & 63;
                float* base = (e < 32) ? g_fkT : g_fvT;
                float* ptr = base + ((long)(b * 8 + h) * 32 + (e & 31)) * NQ + p;
                *(float4*)&ptr[0] = make_float4(r[0], r[1], r[2], r[3]);
                *(float4*)&ptr[4] = make_float4(r[4], r[5], r[6], r[7]);
            }
        } else if (mode == 1) {
            int h = o >> 6, e = o & 63;
            if (e < 32) {
                float* ptr = g_kT + ((long)(b * 8 + h) * 32 + e) * NU + p;
                *(float4*)&ptr[0] = make_float4(r[0], r[1], r[2], r[3]);
                *(float4*)&ptr[4] = make_float4(r[4], r[5], r[6], r[7]);
            } else {
                int d = e - 32;
#pragma unroll
                for (int j = 0; j < 8; j++)
                    g_v[((long)(b * 8 + h) * NU + p + j) * 32 + d] = r[j];
                float* ptr = g_vt + ((long)(b * 256 + h * 32 + d)) * NU + p;
                *(float4*)&ptr[0] = make_float4(r[0], r[1], r[2], r[3]);
                *(float4*)&ptr[4] = make_float4(r[4], r[5], r[6], r[7]);
            }
        } else {
            float* ptr = dst + ((long)(b * 256 + o)) * NQ + p;
            *(float4*)&ptr[0] = make_float4(r[0], r[1], r[2], r[3]);
            *(float4*)&ptr[4] = make_float4(r[4], r[5], r[6], r[7]);
        }
    }
}

// ---------------- topk (unchanged) ------------------------------------------
__global__ void __launch_bounds__(256) topk_kernel() {
    const int bh = blockIdx.x, t = threadIdx.x, w = t >> 5, l = t & 31;
    __shared__ float qm[32], cv[32];
    __shared__ int ci[32], sel[TOPK];
    const float* qb = g_qT + (long)bh * 32 * NQ;
#pragma unroll
    for (int dd = 0; dd < 4; dd++) {
        int d = w * 4 + dd;
        float s = 0.0f;
        const float* row = qb + (long)d * NQ;
        for (int i = l; i < NQ; i += 32) s += row[i];
#pragma unroll
        for (int off = 16; off >= 1; off >>= 1) s += __shfl_xor_sync(~0u, s, off);
        if (l == 0) qm[d] = s * (1.0f / NQ);
    }
    __syncthreads();
    const float* kb = g_kT + (long)bh * 32 * NU;
    float v[4]; int id[4];
#pragma unroll
    for (int r = 0; r < 4; r++) {
        int m = t + r * 256;
        float s = 0.0f;
#pragma unroll
        for (int d = 0; d < 32; d++) s += qm[d] * kb[d * NU + m];
        v[r] = s + gumbel_at((uint32_t)(bh * NU + m));
        id[r] = m;
    }
#pragma unroll
    for (int it = 0; it < TOPK; it++) {
        float lv = v[0]; int li = id[0];
#pragma unroll
        for (int r = 1; r < 4; r++) if (v[r] > lv) { lv = v[r]; li = id[r]; }
#pragma unroll
        for (int off = 16; off >= 1; off >>= 1) {
            float ov = __shfl_xor_sync(~0u, lv, off);
            int oi = __shfl_xor_sync(~0u, li, off);
            if (ov > lv) { lv = ov; li = oi; }
        }
#pragma unroll
        for (int r = 0; r < 4; r++) if (id[r] == li) v[r] = -INFINITY;
        if (l == 0) { cv[w * 4 + it] = lv; ci[w * 4 + it] = li; }
    }
    __syncthreads();
    if (t < 32) {
        float lv = cv[t]; int li = ci[t];
#pragma unroll
        for (int it = 0; it < TOPK; it++) {
            float bv = lv; int bi = li;
#pragma unroll
            for (int off = 16; off >= 1; off >>= 1) {
                float ov = __shfl_xor_sync(~0u, bv, off);
                int oi = __shfl_xor_sync(~0u, bi, off);
                if (ov > bv) { bv = ov; bi = oi; }
            }
            if (li == bi) lv = -INFINITY;
            if (t == 0) sel[it] = bi;
        }
    }
    __syncthreads();
    if (t < NTK) {
        int grp = t / TOPK, kk = t % TOPK;
        int m = sel[kk];
        g_txi[bh * NTK + t] = ((m >> 5) * 2 + (grp >> 1)) * 64 + (m & 31) * 2 + (grp & 1);
    }
}

// ---------------- attention: 128 thr, q64, m128, 8x8 both phases ------------
#define OFF_QT  0        // [32][68]
#define OFF_KT  2176     // [32][132]
#define OFF_VS  6400     // [128][32]
#define OFF_PX  10496    // P[128][68]=8704 / OA[4][64][36]=9216
#define OFF_LR  19712
#define OFF_TXI 19776    // int[16]
#define ATTN_SMEM_FLOATS 19792
#define OFF_OUT OFF_KT          // [64][68]
#define OFF_TK  6528            // [16][32]
#define OFF_TV  7040            // [16][32]
#define OFF_SC  7552            // [64][17]
#define OFF_GS  OFF_PX          // [32][64]
#define OFF_GB  (OFF_PX + 2048)

__global__ void __launch_bounds__(128)
attn_kernel(const float* __restrict__ gate_w, const float* __restrict__ gate_b)
{
    extern __shared__ float sm[];
    const int bh = blockIdx.y, n0 = blockIdx.x * 64, t = threadIdx.x;
    const int b = bh >> 3, h = bh & 7;
    const int qg = t >> 4, mg = t & 15;                      // QK 8q x 8m
    const int ms = t >> 5, qg2 = (t >> 2) & 7, dg = t & 3;   // AV 8q x 8d, 4 m-splits

    const float* qb = g_qT + (long)bh * 32 * NQ + n0;
#pragma unroll
    for (int r = 0; r < 4; r++) {
        int f4 = t + r * 128;
        int d = f4 >> 4, qf = (f4 & 15) << 2;
        *(float4*)&sm[OFF_QT + d * 68 + qf] = *(const float4*)&qb[(long)d * NQ + qf];
    }
    if (t < NTK) ((int*)sm)[OFF_TXI + t] = g_txi[bh * NTK + t];

    u64 acc2[8][4];
    float runl[8];
#pragma unroll
    for (int i = 0; i < 8; i++) {
        runl[i] = 0.0f;
#pragma unroll
        for (int j = 0; j < 4; j++) acc2[i][j] = 0ULL;
    }

    const float* kb = g_kT + (long)bh * 32 * NU;
    const float* vb = g_v  + (long)bh * NU * 32;

    for (int m0 = 0; m0 < NU; m0 += 128) {
        __syncthreads();
#pragma unroll
        for (int r = 0; r < 8; r++) {
            int idx = t + r * 128;
            int d = idx >> 5, c2 = idx & 31;
            int sl = ((c2 >> 1) + ((c2 & 1) << 4) + d) & 31;
            *(float4*)&sm[OFF_KT + d * 132 + sl * 4] =
                *(const float4*)&kb[(long)d * NU + m0 + c2 * 4];
            *(float4*)&sm[OFF_VS + idx * 4] = *(const float4*)&vb[(long)m0 * 32 + idx * 4];
        }
        __syncthreads();

        // QK 8x8
        u64 s2[8][4];
#pragma unroll
        for (int i = 0; i < 8; i++)
#pragma unroll
            for (int j = 0; j < 4; j++) s2[i][j] = 0ULL;
#pragma unroll 4
        for (int k = 0; k < 32; k++) {
            float4 qa = *(const float4*)&sm[OFF_QT + k * 68 + qg * 8];
            float4 qc = *(const float4*)&sm[OFF_QT + k * 68 + qg * 8 + 4];
            ulonglong2 k0 = *(const ulonglong2*)&sm[OFF_KT + k * 132 + ((mg + k) & 31) * 4];
            ulonglong2 k1 = *(const ulonglong2*)&sm[OFF_KT + k * 132 + ((mg + 16 + k) & 31) * 4];
            u64 kp[4] = {k0.x, k0.y, k1.x, k1.y};
            float qv[8] = {qa.x, qa.y, qa.z, qa.w, qc.x, qc.y, qc.z, qc.w};
#pragma unroll
            for (int i = 0; i < 8; i++) {
                u64 qd = dup2(qv[i]);
#pragma unroll
                for (int j = 0; j < 4; j++) fma2(s2[i][j], qd, kp[j]);
            }
        }
        float e[8][8];
#pragma unroll
        for (int i = 0; i < 8; i++)
#pragma unroll
            for (int j = 0; j < 4; j++) {
                float2 f = unpk2(s2[i][j]);
                e[i][j * 2]     = __expf(f.x);
                e[i][j * 2 + 1] = __expf(f.y);
                runl[i] += e[i][j * 2] + e[i][j * 2 + 1];
            }
        // transposed P store: chunk c at slot ((c>>1)+((c&1)<<3)+(m>>3))&15
        {
            int sl0 = ((qg + mg) & 15) * 4, sl1 = ((qg + 8 + mg) & 15) * 4;
#pragma unroll
            for (int j = 0; j < 8; j++) {
                int m = mg * 8 + j;
                *(float4*)&sm[OFF_PX + m * 68 + sl0] =
                    make_float4(e[0][j], e[1][j], e[2][j], e[3][j]);
                *(float4*)&sm[OFF_PX + m * 68 + sl1] =
                    make_float4(e[4][j], e[5][j], e[6][j], e[7][j]);
            }
        }
        __syncthreads();

        // AV 8x8, 4-way m-split
#pragma unroll 4
        for (int st = 0; st < 32; st++) {
            int m = ms * 32 + st, mgp = m >> 3;
            float4 p0 = *(const float4*)&sm[OFF_PX + m * 68 + ((qg2 + mgp) & 15) * 4];
            float4 p1 = *(const float4*)&sm[OFF_PX + m * 68 + ((qg2 + 8 + mgp) & 15) * 4];
            ulonglong2 v0 = *(const ulonglong2*)&sm[OFF_VS + m * 32 + dg * 8];
            ulonglong2 v1 = *(const ulonglong2*)&sm[OFF_VS + m * 32 + dg * 8 + 4];
            u64 vp[4] = {v0.x, v0.y, v1.x, v1.y};
            float pv[8] = {p0.x, p0.y, p0.z, p0.w, p1.x, p1.y, p1.z, p1.w};
#pragma unroll
            for (int i = 0; i < 8; i++) {
                u64 pd = dup2(pv[i]);
#pragma unroll
                for (int j = 0; j < 4; j++) fma2(acc2[i][j], pd, vp[j]);
            }
        }
    }

#pragma unroll
    for (int i = 0; i < 8; i++) {
        float r = runl[i];
        r += __shfl_xor_sync(~0u, r, 8, 16);
        r += __shfl_xor_sync(~0u, r, 4, 16);
        r += __shfl_xor_sync(~0u, r, 2, 16);
        r += __shfl_xor_sync(~0u, r, 1, 16);
        if (mg == 0) sm[OFF_LR + qg * 8 + i] = r;
    }
    __syncthreads();

    // park AV partials OA[ms][q][36]
#pragma unroll
    for (int i = 0; i < 8; i++) {
        int q = qg2 * 8 + i;
        int base = OFF_PX + (ms * 64 + q) * 36 + dg * 8;
        float2 f0 = unpk2(acc2[i][0]), f1 = unpk2(acc2[i][1]);
        float2 f2 = unpk2(acc2[i][2]), f3 = unpk2(acc2[i][3]);
        *(float4*)&sm[base]     = make_float4(f0.x, f0.y, f1.x, f1.y);
        *(float4*)&sm[base + 4] = make_float4(f2.x, f2.y, f3.x, f3.y);
    }
    __syncthreads();

    // reduce -> coarse Out[q][d]; gather fine K/V
#pragma unroll
    for (int r = 0; r < 16; r++) {
        int idx = t + r * 128;
        int q = idx >> 5, d = idx & 31;
        float c = sm[OFF_PX + q * 36 + d] + sm[OFF_PX + (64 + q) * 36 + d]
                + sm[OFF_PX + (128 + q) * 36 + d] + sm[OFF_PX + (192 + q) * 36 + d];
        sm[OFF_OUT + q * 68 + d] = c / sm[OFF_LR + q];
    }
#pragma unroll
    for (int r = 0; r < 4; r++) {
        int idx = t + r * 128;
        int kk = idx >> 5, d = idx & 31;
        int m = ((int*)sm)[OFF_TXI + kk];
        sm[OFF_TK + kk * 32 + d] = g_fkT[((long)bh * 32 + d) * NQ + m];
        sm[OFF_TV + kk * 32 + d] = g_fvT[((long)bh * 32 + d) * NQ + m];
    }
    __syncthreads();

    // fine scores (q = t>>1, 8 keys each); load gate weights
    {
        const int q = t >> 1, kg = t & 1;
        float qv[32];
#pragma unroll
        for (int d = 0; d < 32; d++) qv[d] = sm[OFF_QT + d * 68 + q];
#pragma unroll
        for (int j = 0; j < 8; j++) {
            int kk = kg * 8 + j;
            float s = 0.0f;
#pragma unroll
            for (int d = 0; d < 32; d++) s += qv[d] * sm[OFF_TK + kk * 32 + d];
            sm[OFF_SC + q * 17 + kk] = __expf(s);
        }
    }
#pragma unroll
    for (int r = 0; r < 16; r++) sm[OFF_GS + t + r * 128] = gate_w[t + r * 128];
    if (t < 32) sm[OFF_GB + t] = gate_b[t];
    __syncthreads();
    if (t < 64) {
        float sum = 0.0f;
#pragma unroll
        for (int kk = 0; kk < NTK; kk++) sum += sm[OFF_SC + t * 17 + kk];
        sm[OFF_SC + t * 17 + 16] = 1.0f / sum;
    }
    __syncthreads();
    // refined (q = t>>1, 16 d each)
    {
        const int q = t >> 1, hf = t & 1;
        float inv = sm[OFF_SC + q * 17 + 16];
        float sc[NTK];
#pragma unroll
        for (int kk = 0; kk < NTK; kk++) sc[kk] = sm[OFF_SC + q * 17 + kk];
#pragma unroll
        for (int dd = 0; dd < 16; dd++) {
            int d = hf * 16 + dd;
            float r = 0.0f;
#pragma unroll
            for (int kk = 0; kk < NTK; kk++) r += sc[kk] * sm[OFF_TV + kk * 32 + d];
            sm[OFF_OUT + q * 68 + 32 + d] = r * inv;
        }
    }
    __syncthreads();
    // gate + combine (q = t>>1, 16 d each)
    {
        const int q = t >> 1, hf = t & 1;
        float ov[64];
#pragma unroll
        for (int c4 = 0; c4 < 16; c4++)
            *(float4*)&ov[c4 * 4] = *(const float4*)&sm[OFF_OUT + q * 68 + c4 * 4];
        float res[16];
#pragma unroll
        for (int dd = 0; dd < 16; dd++) {
            int d = hf * 16 + dd;
            float g = sm[OFF_GB + d];
#pragma unroll
            for (int c = 0; c < 64; c++) g += ov[c] * sm[OFF_GS + d * 64 + c];
            float gv = 1.0f / (1.0f + __expf(-g));
            res[dd] = gv * sm[OFF_OUT + q * 68 + 32 + d] + (1.0f - gv) * ov[d];
        }
        __syncthreads();
#pragma unroll
        for (int dd = 0; dd < 16; dd++)
            sm[OFF_OUT + q * 68 + hf * 16 + dd] = res[dd];
    }
    __syncthreads();

    float* xo = g_xout + ((long)(b * 256 + h * 32)) * NQ + n0;
#pragma unroll
    for (int r = 0; r < 16; r++) {
        int idx = t + r * 128;
        int d = idx >> 6, q = idx & 63;
        xo[(long)d * NQ + q] = sm[OFF_OUT + q * 68 + d];
    }
}

// ---------------- depthwise 7x7 + bilinear up + add -------------------------
__global__ void __launch_bounds__(256)
dwupadd_kernel(const float* __restrict__ pe_w, const float* __restrict__ pe_b)
{
    int bc = blockIdx.x, t = threadIdx.x;
    __shared__ float tile[38 * 38], wv[49], vpe[1024];
    const float* src = g_vt + (long)bc * NU;
    for (int idx = t; idx < 38 * 38; idx += 256) {
        int ii = idx / 38 - 3, jj = idx % 38 - 3;
        tile[idx] = (ii >= 0 && ii < 32 && jj >= 0 && jj < 32) ? src[ii * 32 + jj] : 0.0f;
    }
    int c = bc & 255;
    if (t < 49) wv[t] = pe_w[c * 49 + t];
    __syncthreads();
    float bias = pe_b[c];
    for (int idx = t; idx < NU; idx += 256) {
        int i = idx >> 5, j = idx & 31;
        float s = bias;
#pragma unroll
        for (int di = 0; di < 7; di++)
#pragma unroll
            for (int dj = 0; dj < 7; dj++)
                s += tile[(i + di) * 38 + (j + dj)] * wv[di * 7 + dj];
        vpe[idx] = s;
    }
    __syncthreads();
    float* xo = g_xout + (long)bc * NQ;
    for (int idx = t; idx < NQ; idx += 256) {
        int I = idx >> 6, J = idx & 63;
        int i0, i1, j0, j1; float wi0, wi1, wj0, wj1;
        if (I & 1) { i0 = I >> 1; wi0 = 0.75f; i1 = min(i0 + 1, 31); wi1 = 0.25f; }
        else       { i1 = I >> 1; wi1 = 0.75f; i0 = max(i1 - 1, 0);  wi0 = 0.25f; }
        if (J & 1) { j0 = J >> 1; wj0 = 0.75f; j1 = min(j0 + 1, 31); wj1 = 0.25f; }
        else       { j1 = J >> 1; wj1 = 0.75f; j0 = max(j1 - 1, 0);  wj0 = 0.25f; }
        xo[idx] += wi0 * (wj0 * vpe[i0 * 32 + j0] + wj1 * vpe[i0 * 32 + j1])
                 + wi1 * (wj0 * vpe[i1 * 32 + j0] + wj1 * vpe[i1 * 32 + j1]);
    }
}

extern "C" void kernel_launch(void* const* d_in, const int* in_sizes, int n_in,
                              void* d_out, int out_size)
{
    const float* x      = (const float*)d_in[0];
    const float* upper  = (const float*)d_in[1];
    const float* q_w    = (const float*)d_in[2];
    const float* q_b    = (const float*)d_in[3];
    const float* kv_w   = (const float*)d_in[4];
    const float* kv_b   = (const float*)d_in[5];
    const float* proj_w = (const float*)d_in[6];
    const float* proj_b = (const float*)d_in[7];
    const float* pe_w   = (const float*)d_in[8];
    const float* pe_b   = (const float*)d_in[9];
    const float* gate_w = (const float*)d_in[10];
    const float* gate_b = (const float*)d_in[11];
    float* out = (float*)d_out;

    cudaFuncSetAttribute(attn_kernel, cudaFuncAttributeMaxDynamicSharedMemorySize,
                         ATTN_SMEM_FLOATS * 4);

    gemm_kernel<<<dim3(32, 6, 2), 256>>>(x, q_w, q_b, kv_w, kv_b, nullptr, NQ, 0);
    gemm_kernel<<<dim3(8, 4, 2), 256>>>(upper, kv_w, kv_b, nullptr, nullptr, nullptr, NU, 1);
    topk_kernel<<<16, 256>>>();
    attn_kernel<<<dim3(64, 16), 128, ATTN_SMEM_FLOATS * 4>>>(gate_w, gate_b);
    dwupadd_kernel<<<BATCH * DIM, 256>>>(pe_w, pe_b);
    gemm_kernel<<<dim3(32, 2, 2), 256>>>(nullptr, proj_w, proj_b, nullptr, nullptr, out, NQ, 2);
}

// round 9
// speedup vs baseline: 1.4644x; 1.0604x over previous
#include <cuda_runtime.h>
#include <math.h>
#include <stdint.h>

#define BATCH 2
#define DIM 256
#define HEADS 8
#define NQ 4096
#define NU 1024
#define TOPK 4
#define NTK 16
#define ATT_SCALE 0.17677669529663687f

typedef unsigned long long u64;

__device__ __forceinline__ u64 dup2(float a) {
    u64 r; asm("mov.b64 %0, {%1, %1};" : "=l"(r) : "f"(a)); return r;
}
__device__ __forceinline__ void fma2(u64& d, u64 a, u64 b) {
    asm("fma.rn.f32x2 %0, %1, %2, %3;" : "=l"(d) : "l"(a), "l"(b), "l"(d));
}
__device__ __forceinline__ float2 unpk2(u64 v) {
    float2 r; asm("mov.b64 {%0, %1}, %2;" : "=f"(r.x), "=f"(r.y) : "l"(v)); return r;
}

__device__ float g_qT [BATCH*HEADS*32*NQ];
__device__ float g_fkT[BATCH*HEADS*32*NQ];
__device__ float g_fvT[BATCH*HEADS*32*NQ];
__device__ float g_kT [BATCH*HEADS*32*NU];
__device__ float g_v  [BATCH*HEADS*NU*32];
__device__ float g_vt [BATCH*DIM*NU];
__device__ float g_xout[BATCH*DIM*NQ];
__device__ int   g_txi[16*NTK];

__device__ __forceinline__ void threefry2x32_k42(uint32_t x0, uint32_t x1,
                                                 uint32_t& o0, uint32_t& o1) {
    const uint32_t ks1 = 42u, ks2 = 42u ^ 0x1BD11BDAu;
    x1 += ks1;
#define TF_R(r) { x0 += x1; x1 = (x1 << (r)) | (x1 >> (32 - (r))); x1 ^= x0; }
    TF_R(13) TF_R(15) TF_R(26) TF_R(6)
    x0 += ks1; x1 += ks2 + 1u;
    TF_R(17) TF_R(29) TF_R(16) TF_R(24)
    x0 += ks2; x1 += 2u;
    TF_R(13) TF_R(15) TF_R(26) TF_R(6)
    x0 += 0u; x1 += ks1 + 3u;
    TF_R(17) TF_R(29) TF_R(16) TF_R(24)
    x0 += ks1; x1 += ks2 + 4u;
    TF_R(13) TF_R(15) TF_R(26) TF_R(6)
    x0 += ks2; x1 += 5u;
#undef TF_R
    o0 = x0; o1 = x1;
}

__device__ __forceinline__ float gumbel_at(uint32_t l) {
    uint32_t o0, o1;
    threefry2x32_k42(0u, l, o0, o1);
    uint32_t bits = o0 ^ o1;
    float u01 = __uint_as_float((bits >> 9) | 0x3F800000u) - 1.0f;
    const float TINY = 1.17549435e-38f;
    float u = fmaxf(TINY, u01 * (1.0f - TINY) + TINY);
    return -logf(-logf(u));
}

// ---------------- GEMM 128x128, 8x8 microtile, f32x2 ------------------------
__global__ void __launch_bounds__(256, 2)
gemm_kernel(const float* __restrict__ X,
            const float* __restrict__ W1, const float* __restrict__ B1,
            const float* __restrict__ W2, const float* __restrict__ B2,
            float* __restrict__ dst, int P, int mode)
{
    __shared__ float Xs[2][8][128];
    __shared__ float Wt[2][8][132];
    const int b = blockIdx.z, p0 = blockIdx.x * 128, o0 = blockIdx.y * 128;
    const int t = threadIdx.x, to = t >> 4, tp = t & 15;
    const int xc = t >> 5, xp4 = t & 31, woo = t >> 1, whalf = t & 1;

    const float* Xb = (mode == 2) ? (g_xout + (long)b * DIM * P) : (X + (long)b * DIM * P);
    int ow = o0 + woo;
    const float* wptr = (mode == 0 && ow >= 256) ? W2 + (ow - 256) * DIM : W1 + ow * DIM;

    float4 xr = *(const float4*)&Xb[(long)xc * P + p0 + xp4 * 4];
    float4 wr = *(const float4*)&wptr[whalf * 4];

    u64 acc2[8][4];
#pragma unroll
    for (int i = 0; i < 8; i++)
#pragma unroll
        for (int j = 0; j < 4; j++) acc2[i][j] = 0ULL;

    int buf = 0;
    for (int c0 = 0; c0 < DIM; c0 += 8) {
        *(float4*)&Xs[buf][xc][xp4 * 4] = xr;
        Wt[buf][whalf * 4 + 0][woo] = wr.x;
        Wt[buf][whalf * 4 + 1][woo] = wr.y;
        Wt[buf][whalf * 4 + 2][woo] = wr.z;
        Wt[buf][whalf * 4 + 3][woo] = wr.w;
        __syncthreads();
        if (c0 + 8 < DIM) {
            xr = *(const float4*)&Xb[(long)(c0 + 8 + xc) * P + p0 + xp4 * 4];
            wr = *(const float4*)&wptr[c0 + 8 + whalf * 4];
        }
#pragma unroll
        for (int k = 0; k < 8; k++) {
            float4 a0 = *(const float4*)&Wt[buf][k][to * 8];
            float4 a1 = *(const float4*)&Wt[buf][k][to * 8 + 4];
            ulonglong2 xl = *(const ulonglong2*)&Xs[buf][k][tp * 8];
            ulonglong2 xh = *(const ulonglong2*)&Xs[buf][k][tp * 8 + 4];
            u64 xp[4] = {xl.x, xl.y, xh.x, xh.y};
            float av[8] = {a0.x, a0.y, a0.z, a0.w, a1.x, a1.y, a1.z, a1.w};
#pragma unroll
            for (int i = 0; i < 8; i++) {
                u64 ad = dup2(av[i]);
#pragma unroll
                for (int j = 0; j < 4; j++) fma2(acc2[i][j], ad, xp[j]);
            }
        }
        buf ^= 1;
    }

    const int p = p0 + tp * 8;
#pragma unroll
    for (int i = 0; i < 8; i++) {
        int o = o0 + to * 8 + i;
        float bias = (mode == 0 && o >= 256) ? B2[o - 256] : B1[o];
        float r[8];
#pragma unroll
        for (int j = 0; j < 4; j++) {
            float2 f = unpk2(acc2[i][j]);
            r[j * 2] = f.x + bias; r[j * 2 + 1] = f.y + bias;
        }
        if (mode == 0) {
            if (o < 256) {
#pragma unroll
                for (int j = 0; j < 8; j++) r[j] *= ATT_SCALE;
                float* ptr = g_qT + ((long)(b * 8 + (o >> 5)) * 32 + (o & 31)) * NQ + p;
                *(float4*)&ptr[0] = make_float4(r[0], r[1], r[2], r[3]);
                *(float4*)&ptr[4] = make_float4(r[4], r[5], r[6], r[7]);
            } else {
                int e2 = o - 256, h = e2 >> 6, e = e2 & 63;
                float* base = (e < 32) ? g_fkT : g_fvT;
                float* ptr = base + ((long)(b * 8 + h) * 32 + (e & 31)) * NQ + p;
                *(float4*)&ptr[0] = make_float4(r[0], r[1], r[2], r[3]);
                *(float4*)&ptr[4] = make_float4(r[4], r[5], r[6], r[7]);
            }
        } else if (mode == 1) {
            int h = o >> 6, e = o & 63;
            if (e < 32) {
                float* ptr = g_kT + ((long)(b * 8 + h) * 32 + e) * NU + p;
                *(float4*)&ptr[0] = make_float4(r[0], r[1], r[2], r[3]);
                *(float4*)&ptr[4] = make_float4(r[4], r[5], r[6], r[7]);
            } else {
                int d = e - 32;
#pragma unroll
                for (int j = 0; j < 8; j++)
                    g_v[((long)(b * 8 + h) * NU + p + j) * 32 + d] = r[j];
                float* ptr = g_vt + ((long)(b * 256 + h * 32 + d)) * NU + p;
                *(float4*)&ptr[0] = make_float4(r[0], r[1], r[2], r[3]);
                *(float4*)&ptr[4] = make_float4(r[4], r[5], r[6], r[7]);
            }
        } else {
            float* ptr = dst + ((long)(b * 256 + o)) * NQ + p;
            *(float4*)&ptr[0] = make_float4(r[0], r[1], r[2], r[3]);
            *(float4*)&ptr[4] = make_float4(r[4], r[5], r[6], r[7]);
        }
    }
}

// ---------------- topk --------------------------------------------------------
__global__ void __launch_bounds__(256) topk_kernel() {
    const int bh = blockIdx.x, t = threadIdx.x, w = t >> 5, l = t & 31;
    __shared__ float qm[32], cv[32];
    __shared__ int ci[32], sel[TOPK];
    const float* qb = g_qT + (long)bh * 32 * NQ;
#pragma unroll
    for (int dd = 0; dd < 4; dd++) {
        int d = w * 4 + dd;
        float s = 0.0f;
        const float* row = qb + (long)d * NQ;
        for (int i = l; i < NQ; i += 32) s += row[i];
#pragma unroll
        for (int off = 16; off >= 1; off >>= 1) s += __shfl_xor_sync(~0u, s, off);
        if (l == 0) qm[d] = s * (1.0f / NQ);
    }
    __syncthreads();
    const float* kb = g_kT + (long)bh * 32 * NU;
    float v[4]; int id[4];
#pragma unroll
    for (int r = 0; r < 4; r++) {
        int m = t + r * 256;
        float s = 0.0f;
#pragma unroll
        for (int d = 0; d < 32; d++) s += qm[d] * kb[d * NU + m];
        v[r] = s + gumbel_at((uint32_t)(bh * NU + m));
        id[r] = m;
    }
#pragma unroll
    for (int it = 0; it < TOPK; it++) {
        float lv = v[0]; int li = id[0];
#pragma unroll
        for (int r = 1; r < 4; r++) if (v[r] > lv) { lv = v[r]; li = id[r]; }
#pragma unroll
        for (int off = 16; off >= 1; off >>= 1) {
            float ov = __shfl_xor_sync(~0u, lv, off);
            int oi = __shfl_xor_sync(~0u, li, off);
            if (ov > lv) { lv = ov; li = oi; }
        }
#pragma unroll
        for (int r = 0; r < 4; r++) if (id[r] == li) v[r] = -INFINITY;
        if (l == 0) { cv[w * 4 + it] = lv; ci[w * 4 + it] = li; }
    }
    __syncthreads();
    if (t < 32) {
        float lv = cv[t]; int li = ci[t];
#pragma unroll
        for (int it = 0; it < TOPK; it++) {
            float bv = lv; int bi = li;
#pragma unroll
            for (int off = 16; off >= 1; off >>= 1) {
                float ov = __shfl_xor_sync(~0u, bv, off);
                int oi = __shfl_xor_sync(~0u, bi, off);
                if (ov > bv) { bv = ov; bi = oi; }
            }
            if (li == bi) lv = -INFINITY;
            if (t == 0) sel[it] = bi;
        }
    }
    __syncthreads();
    if (t < NTK) {
        int grp = t / TOPK, kk = t % TOPK;
        int m = sel[kk];
        g_txi[bh * NTK + t] = ((m >> 5) * 2 + (grp >> 1)) * 64 + (m & 31) * 2 + (grp & 1);
    }
}

// ---------------- attention: 128 thr, 3 blocks/SM, 74.5KB smem --------------
#define OFF_QT  0        // [32][68]
#define OFF_KT  2176     // [32][128]
#define OFF_VS  6272     // [128][32]
#define OFF_PX  10368    // P[128][64]=8192 / OA[4][64][32]=8192
#define OFF_LR  18560    // [64]
#define OFF_TXI 18624    // int[16]
#define ATTN_SMEM_FLOATS 18640
#define OFF_OUT 2176            // [64][68] (overlays KT + head of VS)
#define OFF_TK  6528            // [16][32]
#define OFF_TV  7040            // [16][32]
#define OFF_SC  7552            // [64][17]
#define OFF_GS  10368           // [32][64] (overlays PX)
#define OFF_GB  12416           // [32]

__global__ void __launch_bounds__(128, 3)
attn_kernel(const float* __restrict__ gate_w, const float* __restrict__ gate_b)
{
    extern __shared__ float sm[];
    const int bh = blockIdx.y, n0 = blockIdx.x * 64, t = threadIdx.x;
    const int b = bh >> 3, h = bh & 7;
    const int qg = t >> 4, mg = t & 15;                      // QK 8q x 8m
    const int ms = t >> 5, qg2 = (t >> 2) & 7, dg = t & 3;   // AV 8q x 8d, 4 m-splits

    const float* qb = g_qT + (long)bh * 32 * NQ + n0;
#pragma unroll
    for (int r = 0; r < 4; r++) {
        int f4 = t + r * 128;
        int d = f4 >> 4, qf = (f4 & 15) << 2;
        *(float4*)&sm[OFF_QT + d * 68 + qf] = *(const float4*)&qb[(long)d * NQ + qf];
    }
    if (t < NTK) ((int*)sm)[OFF_TXI + t] = g_txi[bh * NTK + t];

    u64 acc2[8][4];
    float runl[8];
#pragma unroll
    for (int i = 0; i < 8; i++) {
        runl[i] = 0.0f;
#pragma unroll
        for (int j = 0; j < 4; j++) acc2[i][j] = 0ULL;
    }

    const float* kb = g_kT + (long)bh * 32 * NU;
    const float* vb = g_v  + (long)bh * NU * 32;

    for (int m0 = 0; m0 < NU; m0 += 128) {
        __syncthreads();
#pragma unroll
        for (int r = 0; r < 8; r++) {
            int idx = t + r * 128;
            int d = idx >> 5, c2 = idx & 31;
            int sl = ((c2 >> 1) + ((c2 & 1) << 4) + d) & 31;
            *(float4*)&sm[OFF_KT + d * 128 + sl * 4] =
                *(const float4*)&kb[(long)d * NU + m0 + c2 * 4];
            *(float4*)&sm[OFF_VS + idx * 4] = *(const float4*)&vb[(long)m0 * 32 + idx * 4];
        }
        __syncthreads();

        // QK 8x8
        u64 s2[8][4];
#pragma unroll
        for (int i = 0; i < 8; i++)
#pragma unroll
            for (int j = 0; j < 4; j++) s2[i][j] = 0ULL;
#pragma unroll 4
        for (int k = 0; k < 32; k++) {
            float4 qa = *(const float4*)&sm[OFF_QT + k * 68 + qg * 8];
            float4 qc = *(const float4*)&sm[OFF_QT + k * 68 + qg * 8 + 4];
            ulonglong2 k0 = *(const ulonglong2*)&sm[OFF_KT + k * 128 + ((mg + k) & 31) * 4];
            ulonglong2 k1 = *(const ulonglong2*)&sm[OFF_KT + k * 128 + ((mg + 16 + k) & 31) * 4];
            u64 kp[4] = {k0.x, k0.y, k1.x, k1.y};
            float qv[8] = {qa.x, qa.y, qa.z, qa.w, qc.x, qc.y, qc.z, qc.w};
#pragma unroll
            for (int i = 0; i < 8; i++) {
                u64 qd = dup2(qv[i]);
#pragma unroll
                for (int j = 0; j < 4; j++) fma2(s2[i][j], qd, kp[j]);
            }
        }
        float e[8][8];
#pragma unroll
        for (int i = 0; i < 8; i++)
#pragma unroll
            for (int j = 0; j < 4; j++) {
                float2 f = unpk2(s2[i][j]);
                e[i][j * 2]     = __expf(f.x);
                e[i][j * 2 + 1] = __expf(f.y);
                runl[i] += e[i][j * 2] + e[i][j * 2 + 1];
            }
        {
            int sl0 = ((qg + mg) & 15) * 4, sl1 = ((qg + 8 + mg) & 15) * 4;
#pragma unroll
            for (int j = 0; j < 8; j++) {
                int m = mg * 8 + j;
                *(float4*)&sm[OFF_PX + m * 64 + sl0] =
                    make_float4(e[0][j], e[1][j], e[2][j], e[3][j]);
                *(float4*)&sm[OFF_PX + m * 64 + sl1] =
                    make_float4(e[4][j], e[5][j], e[6][j], e[7][j]);
            }
        }
        __syncthreads();

        // AV 8x8, 4-way m-split
#pragma unroll 4
        for (int st = 0; st < 32; st++) {
            int m = ms * 32 + st, mgp = m >> 3;
            float4 p0 = *(const float4*)&sm[OFF_PX + m * 64 + ((qg2 + mgp) & 15) * 4];
            float4 p1 = *(const float4*)&sm[OFF_PX + m * 64 + ((qg2 + 8 + mgp) & 15) * 4];
            ulonglong2 v0 = *(const ulonglong2*)&sm[OFF_VS + m * 32 + dg * 8];
            ulonglong2 v1 = *(const ulonglong2*)&sm[OFF_VS + m * 32 + dg * 8 + 4];
            u64 vp[4] = {v0.x, v0.y, v1.x, v1.y};
            float pv[8] = {p0.x, p0.y, p0.z, p0.w, p1.x, p1.y, p1.z, p1.w};
#pragma unroll
            for (int i = 0; i < 8; i++) {
                u64 pd = dup2(pv[i]);
#pragma unroll
                for (int j = 0; j < 4; j++) fma2(acc2[i][j], pd, vp[j]);
            }
        }
    }

#pragma unroll
    for (int i = 0; i < 8; i++) {
        float r = runl[i];
        r += __shfl_xor_sync(~0u, r, 8, 16);
        r += __shfl_xor_sync(~0u, r, 4, 16);
        r += __shfl_xor_sync(~0u, r, 2, 16);
        r += __shfl_xor_sync(~0u, r, 1, 16);
        if (mg == 0) sm[OFF_LR + qg * 8 + i] = r;
    }
    __syncthreads();

    // park AV partials OA[ms][q][32]
#pragma unroll
    for (int i = 0; i < 8; i++) {
        int q = qg2 * 8 + i;
        int base = OFF_PX + (ms * 64 + q) * 32 + dg * 8;
        float2 f0 = unpk2(acc2[i][0]), f1 = unpk2(acc2[i][1]);
        float2 f2 = unpk2(acc2[i][2]), f3 = unpk2(acc2[i][3]);
        *(float4*)&sm[base]     = make_float4(f0.x, f0.y, f1.x, f1.y);
        *(float4*)&sm[base + 4] = make_float4(f2.x, f2.y, f3.x, f3.y);
    }
    __syncthreads();

    // reduce -> coarse Out[q][d]; gather fine K/V
#pragma unroll
    for (int r = 0; r < 16; r++) {
        int idx = t + r * 128;
        int q = idx >> 5, d = idx & 31;
        float c = sm[OFF_PX + q * 32 + d] + sm[OFF_PX + 2048 + q * 32 + d]
                + sm[OFF_PX + 4096 + q * 32 + d] + sm[OFF_PX + 6144 + q * 32 + d];
        sm[OFF_OUT + q * 68 + d] = c / sm[OFF_LR + q];
    }
#pragma unroll
    for (int r = 0; r < 4; r++) {
        int idx = t + r * 128;
        int kk = idx >> 5, d = idx & 31;
        int m = ((int*)sm)[OFF_TXI + kk];
        sm[OFF_TK + kk * 32 + d] = g_fkT[((long)bh * 32 + d) * NQ + m];
        sm[OFF_TV + kk * 32 + d] = g_fvT[((long)bh * 32 + d) * NQ + m];
    }
    __syncthreads();

    // fine scores (q = t>>1, 8 keys each); load gate weights
    {
        const int q = t >> 1, kg = t & 1;
        float qv[32];
#pragma unroll
        for (int d = 0; d < 32; d++) qv[d] = sm[OFF_QT + d * 68 + q];
#pragma unroll
        for (int j = 0; j < 8; j++) {
            int kk = kg * 8 + j;
            float s = 0.0f;
#pragma unroll
            for (int d = 0; d < 32; d++) s += qv[d] * sm[OFF_TK + kk * 32 + d];
            sm[OFF_SC + q * 17 + kk] = __expf(s);
        }
    }
#pragma unroll
    for (int r = 0; r < 16; r++) sm[OFF_GS + t + r * 128] = gate_w[t + r * 128];
    if (t < 32) sm[OFF_GB + t] = gate_b[t];
    __syncthreads();
    if (t < 64) {
        float sum = 0.0f;
#pragma unroll
        for (int kk = 0; kk < NTK; kk++) sum += sm[OFF_SC + t * 17 + kk];
        sm[OFF_SC + t * 17 + 16] = 1.0f / sum;
    }
    __syncthreads();
    // refined (q = t>>1, 16 d each)
    {
        const int q = t >> 1, hf = t & 1;
        float inv = sm[OFF_SC + q * 17 + 16];
        float sc[NTK];
#pragma unroll
        for (int kk = 0; kk < NTK; kk++) sc[kk] = sm[OFF_SC + q * 17 + kk];
#pragma unroll
        for (int dd = 0; dd < 16; dd++) {
            int d = hf * 16 + dd;
            float r = 0.0f;
#pragma unroll
            for (int kk = 0; kk < NTK; kk++) r += sc[kk] * sm[OFF_TV + kk * 32 + d];
            sm[OFF_OUT + q * 68 + 32 + d] = r * inv;
        }
    }
    __syncthreads();
    // gate + combine (q = t>>1, 16 d each)
    {
        const int q = t >> 1, hf = t & 1;
        float ov[64];
#pragma unroll
        for (int c4 = 0; c4 < 16; c4++)
            *(float4*)&ov[c4 * 4] = *(const float4*)&sm[OFF_OUT + q * 68 + c4 * 4];
        float res[16];
#pragma unroll
        for (int dd = 0; dd < 16; dd++) {
            int d = hf * 16 + dd;
            float g = sm[OFF_GB + d];
#pragma unroll
            for (int c = 0; c < 64; c++) g += ov[c] * sm[OFF_GS + d * 64 + c];
            float gv = 1.0f / (1.0f + __expf(-g));
            res[dd] = gv * sm[OFF_OUT + q * 68 + 32 + d] + (1.0f - gv) * ov[d];
        }
        __syncthreads();
#pragma unroll
        for (int dd = 0; dd < 16; dd++)
            sm[OFF_OUT + q * 68 + hf * 16 + dd] = res[dd];
    }
    __syncthreads();

    float* xo = g_xout + ((long)(b * 256 + h * 32)) * NQ + n0;
#pragma unroll
    for (int r = 0; r < 16; r++) {
        int idx = t + r * 128;
        int d = idx >> 6, q = idx & 63;
        xo[(long)d * NQ + q] = sm[OFF_OUT + q * 68 + d];
    }
}

// ---------------- depthwise 7x7 + bilinear up + add -------------------------
__global__ void __launch_bounds__(256)
dwupadd_kernel(const float* __restrict__ pe_w, const float* __restrict__ pe_b)
{
    int bc = blockIdx.x, t = threadIdx.x;
    __shared__ float tile[38 * 38], wv[49], vpe[1024];
    const float* src = g_vt + (long)bc * NU;
    for (int idx = t; idx < 38 * 38; idx += 256) {
        int ii = idx / 38 - 3, jj = idx % 38 - 3;
        tile[idx] = (ii >= 0 && ii < 32 && jj >= 0 && jj < 32) ? src[ii * 32 + jj] : 0.0f;
    }
    int c = bc & 255;
    if (t < 49) wv[t] = pe_w[c * 49 + t];
    __syncthreads();
    float bias = pe_b[c];
    for (int idx = t; idx < NU; idx += 256) {
        int i = idx >> 5, j = idx & 31;
        float s = bias;
#pragma unroll
        for (int di = 0; di < 7; di++)
#pragma unroll
            for (int dj = 0; dj < 7; dj++)
                s += tile[(i + di) * 38 + (j + dj)] * wv[di * 7 + dj];
        vpe[idx] = s;
    }
    __syncthreads();
    float* xo = g_xout + (long)bc * NQ;
    for (int idx = t; idx < NQ; idx += 256) {
        int I = idx >> 6, J = idx & 63;
        int i0, i1, j0, j1; float wi0, wi1, wj0, wj1;
        if (I & 1) { i0 = I >> 1; wi0 = 0.75f; i1 = min(i0 + 1, 31); wi1 = 0.25f; }
        else       { i1 = I >> 1; wi1 = 0.75f; i0 = max(i1 - 1, 0);  wi0 = 0.25f; }
        if (J & 1) { j0 = J >> 1; wj0 = 0.75f; j1 = min(j0 + 1, 31); wj1 = 0.25f; }
        else       { j1 = J >> 1; wj1 = 0.75f; j0 = max(j1 - 1, 0);  wj0 = 0.25f; }
        xo[idx] += wi0 * (wj0 * vpe[i0 * 32 + j0] + wj1 * vpe[i0 * 32 + j1])
                 + wi1 * (wj0 * vpe[i1 * 32 + j0] + wj1 * vpe[i1 * 32 + j1]);
    }
}

extern "C" void kernel_launch(void* const* d_in, const int* in_sizes, int n_in,
                              void* d_out, int out_size)
{
    const float* x      = (const float*)d_in[0];
    const float* upper  = (const float*)d_in[1];
    const float* q_w    = (const float*)d_in[2];
    const float* q_b    = (const float*)d_in[3];
    const float* kv_w   = (const float*)d_in[4];
    const float* kv_b   = (const float*)d_in[5];
    const float* proj_w = (const float*)d_in[6];
    const float* proj_b = (const float*)d_in[7];
    const float* pe_w   = (const float*)d_in[8];
    const float* pe_b   = (const float*)d_in[9];
    const float* gate_w = (const float*)d_in[10];
    const float* gate_b = (const float*)d_in[11];
    float* out = (float*)d_out;

    cudaFuncSetAttribute(attn_kernel, cudaFuncAttributeMaxDynamicSharedMemorySize,
                         ATTN_SMEM_FLOATS * 4);

    gemm_kernel<<<dim3(32, 6, 2), 256>>>(x, q_w, q_b, kv_w, kv_b, nullptr, NQ, 0);
    gemm_kernel<<<dim3(8, 4, 2), 256>>>(upper, kv_w, kv_b, nullptr, nullptr, nullptr, NU, 1);
    topk_kernel<<<16, 256>>>();
    attn_kernel<<<dim3(64, 16), 128, ATTN_SMEM_FLOATS * 4>>>(gate_w, gate_b);
    dwupadd_kernel<<<BATCH * DIM, 256>>>(pe_w, pe_b);
    gemm_kernel<<<dim3(32, 2, 2), 256>>>(nullptr, proj_w, proj_b, nullptr, nullptr, out, NQ, 2);
}